// round 1
// baseline (speedup 1.0000x reference)
#include <cuda_runtime.h>
#include <math.h>

// Problem dims (fixed by the reference)
#define Bb 4
#define Tt 2048
#define Hh 1024
#define Nn 16
#define CHUNKS 16
#define Lchunk (Tt / CHUNKS)   // 128
#define Mrows (Bb * Tt)        // 8192

// Scratch (module-scope device memory; no runtime allocation)
__device__ float g_dt[(size_t)Mrows * Hh];            // softplus(u@W^T+b)  32 MB
__device__ float g_q[(size_t)Bb * CHUNKS * Nn * Hh];  // chunk-from-zero end states, 4 MB
__device__ float g_S[(size_t)Bb * CHUNKS * Hh];       // per-chunk sum of dt
__device__ float g_sinit[(size_t)Bb * CHUNKS * Nn * Hh]; // true chunk initial states, 4 MB

__device__ __forceinline__ float ex2f(float x) {
    float y;
    asm("ex2.approx.ftz.f32 %0, %1;" : "=f"(y) : "f"(x));
    return y;
}

__device__ __forceinline__ float softplusf(float z) {
    float az = fabsf(z);
    return fmaxf(z, 0.0f) + log1pf(__expf(-az));
}

// ---------------------------------------------------------------------------
// Kernel 1: Z = u @ W^T ; dt = softplus(Z + b)
// M=8192, N=1024, K=1024, both operands K-major (NT gemm).
// 128x128 tile, BK=8, 256 threads, 8x8 per thread, double-buffered smem.
// ---------------------------------------------------------------------------
#define BM 128
#define BN 128
#define BK 8
#define LDT (BM + 4)   // 132 floats: keeps float4 alignment (528B % 16 == 0), kills STS conflicts

__global__ __launch_bounds__(256, 2)
void gemm_dt_kernel(const float* __restrict__ x, const float* __restrict__ W,
                    const float* __restrict__ bdt) {
    __shared__ float Us[2][BK][LDT];
    __shared__ float Ws[2][BK][LDT];

    const int tid = threadIdx.x;
    const int m0 = blockIdx.y * BM;
    const int n0 = blockIdx.x * BN;
    const int tn = tid & 15;       // 0..15 -> col groups
    const int tm = tid >> 4;       // 0..15 -> row groups

    const int lrow = tid >> 1;         // 0..127
    const int lk   = (tid & 1) * 4;    // 0 or 4

    const float* ug = x + (size_t)(m0 + lrow) * Hh + lk;
    const float* wg = W + (size_t)(n0 + lrow) * Hh + lk;

    float acc[8][8];
#pragma unroll
    for (int i = 0; i < 8; i++)
#pragma unroll
        for (int j = 0; j < 8; j++) acc[i][j] = 0.0f;

    float4 ur = *(const float4*)ug;
    float4 wr = *(const float4*)wg;
    Us[0][lk + 0][lrow] = ur.x; Us[0][lk + 1][lrow] = ur.y;
    Us[0][lk + 2][lrow] = ur.z; Us[0][lk + 3][lrow] = ur.w;
    Ws[0][lk + 0][lrow] = wr.x; Ws[0][lk + 1][lrow] = wr.y;
    Ws[0][lk + 2][lrow] = wr.z; Ws[0][lk + 3][lrow] = wr.w;
    __syncthreads();

    const int NT = Hh / BK;  // 128 k-tiles
    int buf = 0;
    for (int kt = 0; kt < NT; ++kt) {
        if (kt + 1 < NT) {
            ur = *(const float4*)(ug + (size_t)(kt + 1) * BK);
            wr = *(const float4*)(wg + (size_t)(kt + 1) * BK);
        }
#pragma unroll
        for (int kk = 0; kk < BK; ++kk) {
            float a[8], b[8];
            *(float4*)(a)     = *(const float4*)(&Us[buf][kk][tm * 4]);
            *(float4*)(a + 4) = *(const float4*)(&Us[buf][kk][64 + tm * 4]);
            *(float4*)(b)     = *(const float4*)(&Ws[buf][kk][tn * 4]);
            *(float4*)(b + 4) = *(const float4*)(&Ws[buf][kk][64 + tn * 4]);
#pragma unroll
            for (int i = 0; i < 8; ++i)
#pragma unroll
                for (int j = 0; j < 8; ++j)
                    acc[i][j] = fmaf(a[i], b[j], acc[i][j]);
        }
        if (kt + 1 < NT) {
            const int nb = buf ^ 1;
            Us[nb][lk + 0][lrow] = ur.x; Us[nb][lk + 1][lrow] = ur.y;
            Us[nb][lk + 2][lrow] = ur.z; Us[nb][lk + 3][lrow] = ur.w;
            Ws[nb][lk + 0][lrow] = wr.x; Ws[nb][lk + 1][lrow] = wr.y;
            Ws[nb][lk + 2][lrow] = wr.z; Ws[nb][lk + 3][lrow] = wr.w;
        }
        buf ^= 1;
        __syncthreads();
    }

    // Epilogue: bias + softplus, write dt
    float bc[8];
#pragma unroll
    for (int j = 0; j < 4; ++j) {
        bc[j]     = bdt[n0 + tn * 4 + j];
        bc[j + 4] = bdt[n0 + 64 + tn * 4 + j];
    }
#pragma unroll
    for (int i = 0; i < 8; ++i) {
        const int r = m0 + ((i < 4) ? (tm * 4 + i) : (64 + tm * 4 + (i - 4)));
        float4 o0, o1;
        o0.x = softplusf(acc[i][0] + bc[0]);
        o0.y = softplusf(acc[i][1] + bc[1]);
        o0.z = softplusf(acc[i][2] + bc[2]);
        o0.w = softplusf(acc[i][3] + bc[3]);
        o1.x = softplusf(acc[i][4] + bc[4]);
        o1.y = softplusf(acc[i][5] + bc[5]);
        o1.z = softplusf(acc[i][6] + bc[6]);
        o1.w = softplusf(acc[i][7] + bc[7]);
        *(float4*)(&g_dt[(size_t)r * Hh + n0 + tn * 4])      = o0;
        *(float4*)(&g_dt[(size_t)r * Hh + n0 + 64 + tn * 4]) = o1;
    }
}

// ---------------------------------------------------------------------------
// Kernel 2 (phase 1): per (b, h, chunk) run recurrence from zero state.
// Produces q (chunk end state, N values) and S = sum(dt over chunk).
// ---------------------------------------------------------------------------
__global__ __launch_bounds__(256)
void phase1_kernel(const float* __restrict__ x, const float* __restrict__ Alog,
                   const float* __restrict__ Bmat) {
    const int h = blockIdx.x * 256 + threadIdx.x;
    const int c = blockIdx.y;
    const int b = blockIdx.z;

    float A2[Nn], Bv[Nn], s[Nn];
#pragma unroll
    for (int n = 0; n < Nn; ++n) {
        A2[n] = -expf(Alog[h * Nn + n]) * 1.4426950408889634f;  // -exp(A_log)*log2(e)
        Bv[n] = Bmat[h * Nn + n];
        s[n] = 0.0f;
    }
    const size_t base = ((size_t)b * Tt + c * Lchunk) * Hh + h;
    const float* dtp = g_dt + base;
    const float* up  = x + base;

    float S = 0.0f;
    for (int t = 0; t < Lchunk; ++t) {
        const float dtv = dtp[(size_t)t * Hh];
        const float uv  = up[(size_t)t * Hh];
        const float du  = dtv * uv;
        S += dtv;
#pragma unroll
        for (int n = 0; n < Nn; ++n) {
            const float e = ex2f(dtv * A2[n]);
            s[n] = fmaf(e, s[n], Bv[n] * du);
        }
    }
#pragma unroll
    for (int n = 0; n < Nn; ++n)
        g_q[(((size_t)(b * CHUNKS + c)) * Nn + n) * Hh + h] = s[n];
    g_S[(size_t)(b * CHUNKS + c) * Hh + h] = S;
}

// ---------------------------------------------------------------------------
// Kernel 3 (phase 2): sequential combine across chunks per (b, h, n).
// s_in[c+1] = exp(A*S_c)*s_in[c] + q_c ; stores chunk initial states + state_final.
// ---------------------------------------------------------------------------
__global__ __launch_bounds__(256)
void phase2_kernel(const float* __restrict__ Alog, float* __restrict__ out,
                   int write_state) {
    const int idx = blockIdx.x * 256 + threadIdx.x;  // 0..65535
    const int h = idx & (Hh - 1);
    const int u = idx >> 10;      // 0..63
    const int n = u & (Nn - 1);
    const int b = u >> 4;

    const float A2 = -expf(Alog[h * Nn + n]) * 1.4426950408889634f;
    float s = 0.0f;
    for (int c = 0; c < CHUNKS; ++c) {
        const size_t qi = (((size_t)(b * CHUNKS + c)) * Nn + n) * Hh + h;
        g_sinit[qi] = s;
        const float Sc = g_S[(size_t)(b * CHUNKS + c) * Hh + h];
        const float e = ex2f(Sc * A2);
        s = fmaf(e, s, g_q[qi]);
    }
    if (write_state) {
        out[(size_t)Mrows * Hh + ((size_t)b * Hh + h) * Nn + n] = s;
    }
}

// ---------------------------------------------------------------------------
// Kernel 4 (phase 3): re-run each chunk from its true initial state, emit y.
// ---------------------------------------------------------------------------
__global__ __launch_bounds__(256)
void phase3_kernel(const float* __restrict__ x, const float* __restrict__ Alog,
                   const float* __restrict__ Bmat, const float* __restrict__ Cmat,
                   const float* __restrict__ Dvec, float* __restrict__ out) {
    const int h = blockIdx.x * 256 + threadIdx.x;
    const int c = blockIdx.y;
    const int b = blockIdx.z;

    float A2[Nn], Bv[Nn], Cv[Nn], s[Nn];
#pragma unroll
    for (int n = 0; n < Nn; ++n) {
        A2[n] = -expf(Alog[h * Nn + n]) * 1.4426950408889634f;
        Bv[n] = Bmat[h * Nn + n];
        Cv[n] = Cmat[h * Nn + n];
        s[n]  = g_sinit[(((size_t)(b * CHUNKS + c)) * Nn + n) * Hh + h];
    }
    const float Dh = Dvec[h];
    const size_t base = ((size_t)b * Tt + c * Lchunk) * Hh + h;
    const float* dtp = g_dt + base;
    const float* up  = x + base;
    float* yp = out + base;

    for (int t = 0; t < Lchunk; ++t) {
        const float dtv = dtp[(size_t)t * Hh];
        const float uv  = up[(size_t)t * Hh];
        const float du  = dtv * uv;
        float y = Dh * uv;
#pragma unroll
        for (int n = 0; n < Nn; ++n) {
            const float e = ex2f(dtv * A2[n]);
            s[n] = fmaf(e, s[n], Bv[n] * du);
            y = fmaf(s[n], Cv[n], y);
        }
        yp[(size_t)t * Hh] = y;
    }
}

// ---------------------------------------------------------------------------
extern "C" void kernel_launch(void* const* d_in, const int* in_sizes, int n_in,
                              void* d_out, int out_size) {
    const float* x     = (const float*)d_in[0];
    const float* A_log = (const float*)d_in[1];
    const float* B_mat = (const float*)d_in[2];
    const float* C_mat = (const float*)d_in[3];
    const float* D_vec = (const float*)d_in[4];
    const float* W_dt  = (const float*)d_in[5];
    const float* b_dt  = (const float*)d_in[6];
    float* out = (float*)d_out;

    // 1) dt = softplus(u @ W^T + b)
    gemm_dt_kernel<<<dim3(Hh / BN, Mrows / BM), 256>>>(x, W_dt, b_dt);

    // 2) chunked scan
    phase1_kernel<<<dim3(Hh / 256, CHUNKS, Bb), 256>>>(x, A_log, B_mat);

    const int write_state =
        ((size_t)out_size >= (size_t)Mrows * Hh + (size_t)Bb * Hh * Nn) ? 1 : 0;
    phase2_kernel<<<(Bb * Hh * Nn) / 256, 256>>>(A_log, out, write_state);

    phase3_kernel<<<dim3(Hh / 256, CHUNKS, Bb), 256>>>(x, A_log, B_mat, C_mat, D_vec, out);
}

// round 3
// speedup vs baseline: 1.4846x; 1.4846x over previous
#include <cuda_runtime.h>
#include <cuda_bf16.h>
#include <math.h>
#include <stdint.h>

// Problem dims (fixed by the reference)
#define Bb 4
#define Tt 2048
#define Hh 1024
#define Nn 16
#define CHUNKS 64
#define Lchunk (Tt / CHUNKS)   // 32
#define Mrows (Bb * Tt)        // 8192
#define K3 (3 * Hh)            // 3072 (bf16-split extended K)

// ---------------- scratch (module-scope device memory) ----------------
__device__ __nv_bfloat16 g_Aext[(size_t)Mrows * K3];     // [x_hi, x_hi, x_lo]  48MB
__device__ __nv_bfloat16 g_Bext[(size_t)Hh * K3];        // [w_hi, w_lo, w_hi]   6MB
__device__ float g_dt[(size_t)Mrows * Hh];               // dt [m][h]           32MB
__device__ float g_q[(size_t)Bb * CHUNKS * Nn * Hh];     // 16MB
__device__ float g_S[(size_t)Bb * CHUNKS * Hh];          //  1MB
__device__ float g_sinit[(size_t)Bb * CHUNKS * Nn * Hh]; // 16MB

__device__ __forceinline__ float ex2f(float x) {
    float y;
    asm("ex2.approx.ftz.f32 %0, %1;" : "=f"(y) : "f"(x));
    return y;
}
__device__ __forceinline__ float softplusf(float z) {
    float az = fabsf(z);
    return fmaxf(z, 0.0f) + log1pf(__expf(-az));
}
__device__ __forceinline__ void cp_async16(uint32_t saddr, const void* gptr) {
    asm volatile("cp.async.cg.shared.global [%0], [%1], 16;"
                 :: "r"(saddr), "l"(__cvta_generic_to_global(gptr)) : "memory");
}
__device__ __forceinline__ void ldmatrix_x4(uint32_t* r, uint32_t saddr) {
    asm volatile("ldmatrix.sync.aligned.m8n8.x4.shared.b16 {%0,%1,%2,%3}, [%4];"
                 : "=r"(r[0]), "=r"(r[1]), "=r"(r[2]), "=r"(r[3]) : "r"(saddr));
}
__device__ __forceinline__ void mma16816(float* c, const uint32_t* a, uint32_t b0, uint32_t b1) {
    asm volatile(
        "mma.sync.aligned.m16n8k16.row.col.f32.bf16.bf16.f32 "
        "{%0,%1,%2,%3}, {%4,%5,%6,%7}, {%8,%9}, {%0,%1,%2,%3};"
        : "+f"(c[0]), "+f"(c[1]), "+f"(c[2]), "+f"(c[3])
        : "r"(a[0]), "r"(a[1]), "r"(a[2]), "r"(a[3]), "r"(b0), "r"(b1));
}

// ---------------------------------------------------------------------------
// bf16-split conversion kernels
// ---------------------------------------------------------------------------
__global__ __launch_bounds__(256)
void convert_x_kernel(const float* __restrict__ x) {
    size_t i = (size_t)blockIdx.x * 256 + threadIdx.x;  // one float4
    float4 v = ((const float4*)x)[i];
    int m = (int)(i >> 8);
    int k = ((int)i & 255) << 2;
    __nv_bfloat16 h0 = __float2bfloat16(v.x), h1 = __float2bfloat16(v.y);
    __nv_bfloat16 h2 = __float2bfloat16(v.z), h3 = __float2bfloat16(v.w);
    __nv_bfloat16 l0 = __float2bfloat16(v.x - __bfloat162float(h0));
    __nv_bfloat16 l1 = __float2bfloat16(v.y - __bfloat162float(h1));
    __nv_bfloat16 l2 = __float2bfloat16(v.z - __bfloat162float(h2));
    __nv_bfloat16 l3 = __float2bfloat16(v.w - __bfloat162float(h3));
    uint2 hi, lo;
    hi.x = ((uint32_t)__bfloat16_as_ushort(h1) << 16) | __bfloat16_as_ushort(h0);
    hi.y = ((uint32_t)__bfloat16_as_ushort(h3) << 16) | __bfloat16_as_ushort(h2);
    lo.x = ((uint32_t)__bfloat16_as_ushort(l1) << 16) | __bfloat16_as_ushort(l0);
    lo.y = ((uint32_t)__bfloat16_as_ushort(l3) << 16) | __bfloat16_as_ushort(l2);
    size_t base = (size_t)m * K3 + k;
    *(uint2*)(g_Aext + base)          = hi;
    *(uint2*)(g_Aext + base + Hh)     = hi;
    *(uint2*)(g_Aext + base + 2 * Hh) = lo;
}

__global__ __launch_bounds__(256)
void convert_w_kernel(const float* __restrict__ W) {
    size_t i = (size_t)blockIdx.x * 256 + threadIdx.x;
    float4 v = ((const float4*)W)[i];
    int m = (int)(i >> 8);
    int k = ((int)i & 255) << 2;
    __nv_bfloat16 h0 = __float2bfloat16(v.x), h1 = __float2bfloat16(v.y);
    __nv_bfloat16 h2 = __float2bfloat16(v.z), h3 = __float2bfloat16(v.w);
    __nv_bfloat16 l0 = __float2bfloat16(v.x - __bfloat162float(h0));
    __nv_bfloat16 l1 = __float2bfloat16(v.y - __bfloat162float(h1));
    __nv_bfloat16 l2 = __float2bfloat16(v.z - __bfloat162float(h2));
    __nv_bfloat16 l3 = __float2bfloat16(v.w - __bfloat162float(h3));
    uint2 hi, lo;
    hi.x = ((uint32_t)__bfloat16_as_ushort(h1) << 16) | __bfloat16_as_ushort(h0);
    hi.y = ((uint32_t)__bfloat16_as_ushort(h3) << 16) | __bfloat16_as_ushort(h2);
    lo.x = ((uint32_t)__bfloat16_as_ushort(l1) << 16) | __bfloat16_as_ushort(l0);
    lo.y = ((uint32_t)__bfloat16_as_ushort(l3) << 16) | __bfloat16_as_ushort(l2);
    size_t base = (size_t)m * K3 + k;
    *(uint2*)(g_Bext + base)          = hi;   // w_hi
    *(uint2*)(g_Bext + base + Hh)     = lo;   // w_lo
    *(uint2*)(g_Bext + base + 2 * Hh) = hi;   // w_hi
}

// ---------------------------------------------------------------------------
// mma.sync bf16 GEMM: dt = softplus(A_ext @ B_ext^T + b)
// CTA tile 128x128, BK=32, 8 warps (2m x 4n), warp tile 64x32.
// Double-buffered cp.async smem, xor-swizzled for conflict-free ldmatrix.
// ---------------------------------------------------------------------------
#define GBM 128
#define GBN 128
#define GBK 32
#define NKT (K3 / GBK)             // 96
#define A_ELEMS (GBM * GBK)        // 4096 bf16 = 8KB
#define STAGE_ELEMS (2 * A_ELEMS)  // 8192 bf16 = 16KB

// smem byte offset within a 128x32 bf16 tile: row r (0..127), 16B-chunk c (0..3)
__device__ __forceinline__ uint32_t swz(int r, int c) {
    return (uint32_t)(r * 64 + ((c ^ ((r >> 1) & 3)) << 4));
}

__global__ __launch_bounds__(256, 2)
void gemm_mma_kernel(const float* __restrict__ bdt) {
    __shared__ __align__(16) __nv_bfloat16 sm[2][STAGE_ELEMS];

    const int tid = threadIdx.x;
    const int wid = tid >> 5, lane = tid & 31;
    const int n0 = blockIdx.x * GBN;
    const int m0 = blockIdx.y * GBM;
    const int wm = (wid >> 2) * 64;   // warp m offset in tile
    const int wn = (wid & 3) * 32;    // warp n offset in tile

    const uint32_t s0 = (uint32_t)__cvta_generic_to_shared(&sm[0][0]);
    const uint32_t sstage = STAGE_ELEMS * 2;  // bytes per stage (16KB)

    const __nv_bfloat16* Abase = g_Aext + (size_t)m0 * K3;
    const __nv_bfloat16* Bbase = g_Bext + (size_t)n0 * K3;

    // per-thread load slots: 4 chunks of 16B (2 A + 2 B)
    const int ch0 = tid;          // A chunk ids: tid, tid+256 (of 512)
    auto issue_loads = [&](int kt, int stage) {
        const uint32_t sA = s0 + stage * sstage;
        const uint32_t sB = sA + A_ELEMS * 2;
        const __nv_bfloat16* Ag = Abase + kt * GBK;
        const __nv_bfloat16* Bg = Bbase + kt * GBK;
#pragma unroll
        for (int i = 0; i < 2; i++) {
            int ch = ch0 + i * 256;
            int r = ch >> 2, c = ch & 3;
            cp_async16(sA + swz(r, c), Ag + (size_t)r * K3 + c * 8);
        }
#pragma unroll
        for (int i = 0; i < 2; i++) {
            int ch = ch0 + i * 256;
            int r = ch >> 2, c = ch & 3;
            cp_async16(sB + swz(r, c), Bg + (size_t)r * K3 + c * 8);
        }
        asm volatile("cp.async.commit_group;" ::: "memory");
    };

    float acc[4][4][4];
#pragma unroll
    for (int i = 0; i < 4; i++)
#pragma unroll
        for (int j = 0; j < 4; j++)
#pragma unroll
            for (int k = 0; k < 4; k++) acc[i][j][k] = 0.0f;

    issue_loads(0, 0);

    const int lrow = lane & 15;            // ldmatrix row within 16-row group
    const int lkh  = (lane >> 4) & 1;      // k-half select

    for (int kt = 0; kt < NKT; kt++) {
        const int stage = kt & 1;
        if (kt + 1 < NKT) issue_loads(kt + 1, stage ^ 1);
        if (kt + 1 < NKT) {
            asm volatile("cp.async.wait_group 1;" ::: "memory");
        } else {
            asm volatile("cp.async.wait_group 0;" ::: "memory");
        }
        __syncthreads();

        const uint32_t sA = s0 + stage * sstage;
        const uint32_t sB = sA + A_ELEMS * 2;

#pragma unroll
        for (int ks = 0; ks < 2; ks++) {
            const int c16 = ks * 2 + lkh;
            uint32_t a[4][4];
#pragma unroll
            for (int mb = 0; mb < 4; mb++) {
                const int r = wm + mb * 16 + lrow;
                ldmatrix_x4(a[mb], sA + swz(r, c16));
            }
            uint32_t bf[2][4];
#pragma unroll
            for (int nb = 0; nb < 2; nb++) {
                const int r = wn + nb * 16 + lrow;
                ldmatrix_x4(bf[nb], sB + swz(r, c16));
            }
#pragma unroll
            for (int mb = 0; mb < 4; mb++)
#pragma unroll
                for (int j = 0; j < 4; j++)
                    mma16816(acc[mb][j], a[mb], bf[j >> 1][j & 1], bf[j >> 1][(j & 1) + 2]);
        }
        __syncthreads();
    }

    // Epilogue: bias + softplus, float2 stores to dt[m][h]
    const int g = lane >> 2;        // row within m8 group
    const int t = lane & 3;         // col pair
#pragma unroll
    for (int j = 0; j < 4; j++) {
        const int h = n0 + wn + j * 8 + 2 * t;
        const float b0 = __ldg(&bdt[h]);
        const float b1 = __ldg(&bdt[h + 1]);
#pragma unroll
        for (int mb = 0; mb < 4; mb++) {
            const int m = m0 + wm + mb * 16 + g;
            float2 v0, v1;
            v0.x = softplusf(acc[mb][j][0] + b0);
            v0.y = softplusf(acc[mb][j][1] + b1);
            v1.x = softplusf(acc[mb][j][2] + b0);
            v1.y = softplusf(acc[mb][j][3] + b1);
            *(float2*)(&g_dt[(size_t)m * Hh + h])       = v0;
            *(float2*)(&g_dt[(size_t)(m + 8) * Hh + h]) = v1;
        }
    }
}

// ---------------------------------------------------------------------------
// Phase 1: per (b, h, chunk) recurrence from zero state -> q, S
// ---------------------------------------------------------------------------
__global__ __launch_bounds__(256)
void phase1_kernel(const float* __restrict__ x, const float* __restrict__ Alog,
                   const float* __restrict__ Bmat) {
    const int h = blockIdx.x * 256 + threadIdx.x;
    const int c = blockIdx.y;
    const int b = blockIdx.z;

    float A2[Nn], Bv[Nn], s[Nn];
#pragma unroll
    for (int n = 0; n < Nn; ++n) {
        A2[n] = -expf(Alog[h * Nn + n]) * 1.4426950408889634f;
        Bv[n] = Bmat[h * Nn + n];
        s[n] = 0.0f;
    }
    const size_t base = ((size_t)b * Tt + c * Lchunk) * Hh + h;
    const float* dtp = g_dt + base;
    const float* up  = x + base;

    float S = 0.0f;
    for (int tt = 0; tt < Lchunk; ++tt) {
        const float dtv = dtp[(size_t)tt * Hh];
        const float uv  = up[(size_t)tt * Hh];
        const float du  = dtv * uv;
        S += dtv;
#pragma unroll
        for (int n = 0; n < Nn; ++n) {
            const float e = ex2f(dtv * A2[n]);
            s[n] = fmaf(e, s[n], Bv[n] * du);
        }
    }
#pragma unroll
    for (int n = 0; n < Nn; ++n)
        g_q[(((size_t)(b * CHUNKS + c)) * Nn + n) * Hh + h] = s[n];
    g_S[(size_t)(b * CHUNKS + c) * Hh + h] = S;
}

// ---------------------------------------------------------------------------
// Phase 2: sequential combine across chunks per (b, h, n)
// ---------------------------------------------------------------------------
__global__ __launch_bounds__(256)
void phase2_kernel(const float* __restrict__ Alog, float* __restrict__ out,
                   int write_state) {
    const int idx = blockIdx.x * 256 + threadIdx.x;
    const int h = idx & (Hh - 1);
    const int u = idx >> 10;
    const int n = u & (Nn - 1);
    const int b = u >> 4;

    const float A2 = -expf(Alog[h * Nn + n]) * 1.4426950408889634f;
    float s = 0.0f;
    for (int c = 0; c < CHUNKS; ++c) {
        const size_t qi = (((size_t)(b * CHUNKS + c)) * Nn + n) * Hh + h;
        g_sinit[qi] = s;
        const float Sc = g_S[(size_t)(b * CHUNKS + c) * Hh + h];
        const float e = ex2f(Sc * A2);
        s = fmaf(e, s, g_q[qi]);
    }
    if (write_state) {
        out[(size_t)Mrows * Hh + ((size_t)b * Hh + h) * Nn + n] = s;
    }
}

// ---------------------------------------------------------------------------
// Phase 3: re-run each chunk from its true initial state, emit y
// ---------------------------------------------------------------------------
__global__ __launch_bounds__(256)
void phase3_kernel(const float* __restrict__ x, const float* __restrict__ Alog,
                   const float* __restrict__ Bmat, const float* __restrict__ Cmat,
                   const float* __restrict__ Dvec, float* __restrict__ out) {
    const int h = blockIdx.x * 256 + threadIdx.x;
    const int c = blockIdx.y;
    const int b = blockIdx.z;

    float A2[Nn], Bv[Nn], Cv[Nn], s[Nn];
#pragma unroll
    for (int n = 0; n < Nn; ++n) {
        A2[n] = -expf(Alog[h * Nn + n]) * 1.4426950408889634f;
        Bv[n] = Bmat[h * Nn + n];
        Cv[n] = Cmat[h * Nn + n];
        s[n]  = g_sinit[(((size_t)(b * CHUNKS + c)) * Nn + n) * Hh + h];
    }
    const float Dh = Dvec[h];
    const size_t base = ((size_t)b * Tt + c * Lchunk) * Hh + h;
    const float* dtp = g_dt + base;
    const float* up  = x + base;
    float* yp = out + base;

    for (int tt = 0; tt < Lchunk; ++tt) {
        const float dtv = dtp[(size_t)tt * Hh];
        const float uv  = up[(size_t)tt * Hh];
        const float du  = dtv * uv;
        float y = Dh * uv;
#pragma unroll
        for (int n = 0; n < Nn; ++n) {
            const float e = ex2f(dtv * A2[n]);
            s[n] = fmaf(e, s[n], Bv[n] * du);
            y = fmaf(s[n], Cv[n], y);
        }
        yp[(size_t)tt * Hh] = y;
    }
}

// ---------------------------------------------------------------------------
extern "C" void kernel_launch(void* const* d_in, const int* in_sizes, int n_in,
                              void* d_out, int out_size) {
    const float* x     = (const float*)d_in[0];
    const float* A_log = (const float*)d_in[1];
    const float* B_mat = (const float*)d_in[2];
    const float* C_mat = (const float*)d_in[3];
    const float* D_vec = (const float*)d_in[4];
    const float* W_dt  = (const float*)d_in[5];
    const float* b_dt  = (const float*)d_in[6];
    float* out = (float*)d_out;

    // bf16-split operand prep
    convert_x_kernel<<<(Mrows * Hh / 4) / 256, 256>>>(x);
    convert_w_kernel<<<(Hh * Hh / 4) / 256, 256>>>(W_dt);

    // tensor-core GEMM + softplus epilogue -> g_dt [m][h]
    gemm_mma_kernel<<<dim3(Hh / GBN, Mrows / GBM), 256>>>(b_dt);

    // chunked scan
    phase1_kernel<<<dim3(Hh / 256, CHUNKS, Bb), 256>>>(x, A_log, B_mat);

    const int write_state =
        ((size_t)out_size >= (size_t)Mrows * Hh + (size_t)Bb * Hh * Nn) ? 1 : 0;
    phase2_kernel<<<(Bb * Hh * Nn) / 256, 256>>>(A_log, out, write_state);

    phase3_kernel<<<dim3(Hh / 256, CHUNKS, Bb), 256>>>(x, A_log, B_mat, C_mat, D_vec, out);
}

// round 4
// speedup vs baseline: 1.8361x; 1.2368x over previous
#include <cuda_runtime.h>
#include <cuda_fp16.h>
#include <math.h>
#include <stdint.h>

// Problem dims (fixed by the reference)
#define Bb 4
#define Tt 2048
#define Hh 1024
#define Nn 16
#define CHUNKS 64
#define Lchunk (Tt / CHUNKS)   // 32
#define Mrows (Bb * Tt)        // 8192
#define K2 (2 * Hh)            // 2048 (fp16 2-term split K)

// ---------------- scratch (module-scope device memory) ----------------
__device__ __half g_Aext[(size_t)Mrows * K2];            // [x_hi, x_lo]  32MB
__device__ __half g_Bext[(size_t)Hh * K2];               // [w_hi, w_hi]   4MB
__device__ float2 g_zu[(size_t)Mrows * Hh];              // packed {dt,u} 64MB
__device__ float g_q[(size_t)Bb * CHUNKS * Nn * Hh];     // 16MB
__device__ float g_S[(size_t)Bb * CHUNKS * Hh];          //  1MB
__device__ float g_sinit[(size_t)Bb * CHUNKS * Nn * Hh]; // 16MB

__device__ __forceinline__ float ex2f(float x) {
    float y;
    asm("ex2.approx.ftz.f32 %0, %1;" : "=f"(y) : "f"(x));
    return y;
}
__device__ __forceinline__ float softplusf(float z) {
    float az = fabsf(z);
    return fmaxf(z, 0.0f) + log1pf(__expf(-az));
}
__device__ __forceinline__ void cp_async16(uint32_t saddr, const void* gptr) {
    asm volatile("cp.async.cg.shared.global [%0], [%1], 16;"
                 :: "r"(saddr), "l"(__cvta_generic_to_global(gptr)) : "memory");
}
__device__ __forceinline__ void ldmatrix_x4(uint32_t* r, uint32_t saddr) {
    asm volatile("ldmatrix.sync.aligned.m8n8.x4.shared.b16 {%0,%1,%2,%3}, [%4];"
                 : "=r"(r[0]), "=r"(r[1]), "=r"(r[2]), "=r"(r[3]) : "r"(saddr));
}
__device__ __forceinline__ void mma16816(float* c, const uint32_t* a, uint32_t b0, uint32_t b1) {
    asm volatile(
        "mma.sync.aligned.m16n8k16.row.col.f32.f16.f16.f32 "
        "{%0,%1,%2,%3}, {%4,%5,%6,%7}, {%8,%9}, {%0,%1,%2,%3};"
        : "+f"(c[0]), "+f"(c[1]), "+f"(c[2]), "+f"(c[3])
        : "r"(a[0]), "r"(a[1]), "r"(a[2]), "r"(a[3]), "r"(b0), "r"(b1));
}

// ---------------------------------------------------------------------------
// fp16 2-term split conversion kernels
// ---------------------------------------------------------------------------
__global__ __launch_bounds__(256)
void convert_x_kernel(const float* __restrict__ x) {
    size_t i = (size_t)blockIdx.x * 256 + threadIdx.x;  // one float4
    float4 v = ((const float4*)x)[i];
    int m = (int)(i >> 8);
    int k = ((int)i & 255) << 2;
    __half h0 = __float2half_rn(v.x), h1 = __float2half_rn(v.y);
    __half h2 = __float2half_rn(v.z), h3 = __float2half_rn(v.w);
    __half l0 = __float2half_rn(v.x - __half2float(h0));
    __half l1 = __float2half_rn(v.y - __half2float(h1));
    __half l2 = __float2half_rn(v.z - __half2float(h2));
    __half l3 = __float2half_rn(v.w - __half2float(h3));
    uint2 hi, lo;
    hi.x = ((uint32_t)__half_as_ushort(h1) << 16) | __half_as_ushort(h0);
    hi.y = ((uint32_t)__half_as_ushort(h3) << 16) | __half_as_ushort(h2);
    lo.x = ((uint32_t)__half_as_ushort(l1) << 16) | __half_as_ushort(l0);
    lo.y = ((uint32_t)__half_as_ushort(l3) << 16) | __half_as_ushort(l2);
    size_t base = (size_t)m * K2 + k;
    *(uint2*)(g_Aext + base)      = hi;   // x_hi
    *(uint2*)(g_Aext + base + Hh) = lo;   // x_lo
}

__global__ __launch_bounds__(256)
void convert_w_kernel(const float* __restrict__ W) {
    size_t i = (size_t)blockIdx.x * 256 + threadIdx.x;
    float4 v = ((const float4*)W)[i];
    int m = (int)(i >> 8);
    int k = ((int)i & 255) << 2;
    __half h0 = __float2half_rn(v.x), h1 = __float2half_rn(v.y);
    __half h2 = __float2half_rn(v.z), h3 = __float2half_rn(v.w);
    uint2 hi;
    hi.x = ((uint32_t)__half_as_ushort(h1) << 16) | __half_as_ushort(h0);
    hi.y = ((uint32_t)__half_as_ushort(h3) << 16) | __half_as_ushort(h2);
    size_t base = (size_t)m * K2 + k;
    *(uint2*)(g_Bext + base)      = hi;   // w_hi (both K-halves identical)
    *(uint2*)(g_Bext + base + Hh) = hi;
}

// ---------------------------------------------------------------------------
// mma.sync fp16 GEMM: z = A_ext @ B_ext^T ; zu = {softplus(z+b), u}
// CTA tile 128x128, BK=32, 8 warps (2m x 4n), warp tile 64x32.
// 4-stage cp.async pipeline, single __syncthreads per K-iter.
// ---------------------------------------------------------------------------
#define GBM 128
#define GBN 128
#define GBK 32
#define NKT (K2 / GBK)             // 64
#define NSTAGE 4
#define A_ELEMS (GBM * GBK)        // 4096 halves = 8KB
#define STAGE_ELEMS (2 * A_ELEMS)  // 8192 halves = 16KB
#define STAGE_BYTES (STAGE_ELEMS * 2)
#define GEMM_DYN_SMEM (NSTAGE * STAGE_BYTES)  // 64KB

// smem byte offset within a 128x32 fp16 tile: row r (0..127), 16B-chunk c (0..3)
__device__ __forceinline__ uint32_t swz(int r, int c) {
    return (uint32_t)(r * 64 + ((c ^ ((r >> 1) & 3)) << 4));
}

__global__ __launch_bounds__(256, 2)
void gemm_mma_kernel(const float* __restrict__ x, const float* __restrict__ bdt) {
    extern __shared__ __align__(16) char dsm[];

    const int tid = threadIdx.x;
    const int wid = tid >> 5, lane = tid & 31;
    const int n0 = blockIdx.x * GBN;
    const int m0 = blockIdx.y * GBM;
    const int wm = (wid >> 2) * 64;   // warp m offset
    const int wn = (wid & 3) * 32;    // warp n offset

    const uint32_t s0 = (uint32_t)__cvta_generic_to_shared(dsm);

    const __half* Abase = g_Aext + (size_t)m0 * K2;
    const __half* Bbase = g_Bext + (size_t)n0 * K2;

    const int ch0 = tid;
    auto issue_loads = [&](int kt, int stage) {
        const uint32_t sA = s0 + stage * STAGE_BYTES;
        const uint32_t sB = sA + A_ELEMS * 2;
        const __half* Ag = Abase + kt * GBK;
        const __half* Bg = Bbase + kt * GBK;
#pragma unroll
        for (int i = 0; i < 2; i++) {
            int ch = ch0 + i * 256;
            int r = ch >> 2, c = ch & 3;
            cp_async16(sA + swz(r, c), Ag + (size_t)r * K2 + c * 8);
        }
#pragma unroll
        for (int i = 0; i < 2; i++) {
            int ch = ch0 + i * 256;
            int r = ch >> 2, c = ch & 3;
            cp_async16(sB + swz(r, c), Bg + (size_t)r * K2 + c * 8);
        }
        asm volatile("cp.async.commit_group;" ::: "memory");
    };

    float acc[4][4][4];
#pragma unroll
    for (int i = 0; i < 4; i++)
#pragma unroll
        for (int j = 0; j < 4; j++)
#pragma unroll
            for (int k = 0; k < 4; k++) acc[i][j][k] = 0.0f;

    // prologue: NSTAGE-1 stages in flight
#pragma unroll
    for (int s = 0; s < NSTAGE - 1; s++) issue_loads(s, s);

    const int lrow = lane & 15;
    const int lkh  = (lane >> 4) & 1;

    for (int kt = 0; kt < NKT; kt++) {
        asm volatile("cp.async.wait_group %0;" :: "n"(NSTAGE - 2) : "memory");
        __syncthreads();

        if (kt + NSTAGE - 1 < NKT) {
            issue_loads(kt + NSTAGE - 1, (kt + NSTAGE - 1) & (NSTAGE - 1));
        } else {
            asm volatile("cp.async.commit_group;" ::: "memory");
        }

        const int stage = kt & (NSTAGE - 1);
        const uint32_t sA = s0 + stage * STAGE_BYTES;
        const uint32_t sB = sA + A_ELEMS * 2;

#pragma unroll
        for (int ks = 0; ks < 2; ks++) {
            const int c16 = ks * 2 + lkh;
            uint32_t a[4][4];
#pragma unroll
            for (int mb = 0; mb < 4; mb++)
                ldmatrix_x4(a[mb], sA + swz(wm + mb * 16 + lrow, c16));
            uint32_t bf[2][4];
#pragma unroll
            for (int nb = 0; nb < 2; nb++)
                ldmatrix_x4(bf[nb], sB + swz(wn + nb * 16 + lrow, c16));
#pragma unroll
            for (int mb = 0; mb < 4; mb++)
#pragma unroll
                for (int j = 0; j < 4; j++)
                    mma16816(acc[mb][j], a[mb], bf[j >> 1][j & 1], bf[j >> 1][(j & 1) + 2]);
        }
    }

    // Epilogue: bias + softplus; pack {dt, u} -> g_zu (float4 = 2 float2 elems)
    const int g = lane >> 2;
    const int t = lane & 3;
#pragma unroll
    for (int j = 0; j < 4; j++) {
        const int h = n0 + wn + j * 8 + 2 * t;
        const float b0 = __ldg(&bdt[h]);
        const float b1 = __ldg(&bdt[h + 1]);
#pragma unroll
        for (int mb = 0; mb < 4; mb++) {
            const int m = m0 + wm + mb * 16 + g;
            const float2 u0 = *(const float2*)(x + (size_t)m * Hh + h);
            const float2 u1 = *(const float2*)(x + (size_t)(m + 8) * Hh + h);
            float4 o0, o1;
            o0.x = softplusf(acc[mb][j][0] + b0); o0.y = u0.x;
            o0.z = softplusf(acc[mb][j][1] + b1); o0.w = u0.y;
            o1.x = softplusf(acc[mb][j][2] + b0); o1.y = u1.x;
            o1.z = softplusf(acc[mb][j][3] + b1); o1.w = u1.y;
            *(float4*)(&g_zu[(size_t)m * Hh + h])       = o0;
            *(float4*)(&g_zu[(size_t)(m + 8) * Hh + h]) = o1;
        }
    }
}

// ---------------------------------------------------------------------------
// Phase 1: per (b, h, chunk) recurrence from zero state -> q, S
// ---------------------------------------------------------------------------
__global__ __launch_bounds__(256)
void phase1_kernel(const float* __restrict__ Alog, const float* __restrict__ Bmat) {
    const int h = blockIdx.x * 256 + threadIdx.x;
    const int c = blockIdx.y;
    const int b = blockIdx.z;

    float A2[Nn], Bv[Nn], s[Nn];
#pragma unroll
    for (int n = 0; n < Nn; ++n) {
        A2[n] = -expf(Alog[h * Nn + n]) * 1.4426950408889634f;
        Bv[n] = Bmat[h * Nn + n];
        s[n] = 0.0f;
    }
    const float2* zp = g_zu + ((size_t)b * Tt + c * Lchunk) * Hh + h;

    float S = 0.0f;
    float2 cur = zp[0];
#pragma unroll 4
    for (int tt = 0; tt < Lchunk; ++tt) {
        float2 nxt = (tt + 1 < Lchunk) ? zp[(size_t)(tt + 1) * Hh] : cur;
        const float dtv = cur.x;
        const float du  = dtv * cur.y;
        S += dtv;
#pragma unroll
        for (int n = 0; n < Nn; ++n) {
            const float e = ex2f(dtv * A2[n]);
            s[n] = fmaf(e, s[n], Bv[n] * du);
        }
        cur = nxt;
    }
#pragma unroll
    for (int n = 0; n < Nn; ++n)
        g_q[(((size_t)(b * CHUNKS + c)) * Nn + n) * Hh + h] = s[n];
    g_S[(size_t)(b * CHUNKS + c) * Hh + h] = S;
}

// ---------------------------------------------------------------------------
// Phase 2: sequential combine across chunks per (b, h, n)
// ---------------------------------------------------------------------------
__global__ __launch_bounds__(256)
void phase2_kernel(const float* __restrict__ Alog, float* __restrict__ out,
                   int write_state) {
    const int idx = blockIdx.x * 256 + threadIdx.x;
    const int h = idx & (Hh - 1);
    const int u = idx >> 10;
    const int n = u & (Nn - 1);
    const int b = u >> 4;

    const float A2 = -expf(Alog[h * Nn + n]) * 1.4426950408889634f;
    float s = 0.0f;
    for (int c = 0; c < CHUNKS; ++c) {
        const size_t qi = (((size_t)(b * CHUNKS + c)) * Nn + n) * Hh + h;
        g_sinit[qi] = s;
        const float Sc = g_S[(size_t)(b * CHUNKS + c) * Hh + h];
        const float e = ex2f(Sc * A2);
        s = fmaf(e, s, g_q[qi]);
    }
    if (write_state) {
        out[(size_t)Mrows * Hh + ((size_t)b * Hh + h) * Nn + n] = s;
    }
}

// ---------------------------------------------------------------------------
// Phase 3: re-run each chunk from its true initial state, emit y
// ---------------------------------------------------------------------------
__global__ __launch_bounds__(256)
void phase3_kernel(const float* __restrict__ Alog, const float* __restrict__ Bmat,
                   const float* __restrict__ Cmat, const float* __restrict__ Dvec,
                   float* __restrict__ out) {
    const int h = blockIdx.x * 256 + threadIdx.x;
    const int c = blockIdx.y;
    const int b = blockIdx.z;

    float A2[Nn], Bv[Nn], Cv[Nn], s[Nn];
#pragma unroll
    for (int n = 0; n < Nn; ++n) {
        A2[n] = -expf(Alog[h * Nn + n]) * 1.4426950408889634f;
        Bv[n] = Bmat[h * Nn + n];
        Cv[n] = Cmat[h * Nn + n];
        s[n]  = g_sinit[(((size_t)(b * CHUNKS + c)) * Nn + n) * Hh + h];
    }
    const float Dh = Dvec[h];
    const size_t base = ((size_t)b * Tt + c * Lchunk) * Hh + h;
    const float2* zp = g_zu + base;
    float* yp = out + base;

    float2 cur = zp[0];
#pragma unroll 4
    for (int tt = 0; tt < Lchunk; ++tt) {
        float2 nxt = (tt + 1 < Lchunk) ? zp[(size_t)(tt + 1) * Hh] : cur;
        const float dtv = cur.x;
        const float uv  = cur.y;
        const float du  = dtv * uv;
        float y = Dh * uv;
#pragma unroll
        for (int n = 0; n < Nn; ++n) {
            const float e = ex2f(dtv * A2[n]);
            s[n] = fmaf(e, s[n], Bv[n] * du);
            y = fmaf(s[n], Cv[n], y);
        }
        yp[(size_t)tt * Hh] = y;
        cur = nxt;
    }
}

// ---------------------------------------------------------------------------
extern "C" void kernel_launch(void* const* d_in, const int* in_sizes, int n_in,
                              void* d_out, int out_size) {
    const float* x     = (const float*)d_in[0];
    const float* A_log = (const float*)d_in[1];
    const float* B_mat = (const float*)d_in[2];
    const float* C_mat = (const float*)d_in[3];
    const float* D_vec = (const float*)d_in[4];
    const float* W_dt  = (const float*)d_in[5];
    const float* b_dt  = (const float*)d_in[6];
    float* out = (float*)d_out;

    // fp16 2-term split operand prep
    convert_x_kernel<<<(Mrows * Hh / 4) / 256, 256>>>(x);
    convert_w_kernel<<<(Hh * Hh / 4) / 256, 256>>>(W_dt);

    // tensor-core GEMM + softplus epilogue -> packed g_zu {dt,u}
    static int smem_set = 0;
    if (!smem_set) {
        cudaFuncSetAttribute(gemm_mma_kernel,
                             cudaFuncAttributeMaxDynamicSharedMemorySize, GEMM_DYN_SMEM);
        smem_set = 1;
    }
    gemm_mma_kernel<<<dim3(Hh / GBN, Mrows / GBM), 256, GEMM_DYN_SMEM>>>(x, b_dt);

    // chunked scan
    phase1_kernel<<<dim3(Hh / 256, CHUNKS, Bb), 256>>>(A_log, B_mat);

    const int write_state =
        ((size_t)out_size >= (size_t)Mrows * Hh + (size_t)Bb * Hh * Nn) ? 1 : 0;
    phase2_kernel<<<(Bb * Hh * Nn) / 256, 256>>>(A_log, out, write_state);

    phase3_kernel<<<dim3(Hh / 256, CHUNKS, Bb), 256>>>(A_log, B_mat, C_mat, D_vec, out);
}

// round 5
// speedup vs baseline: 1.9000x; 1.0348x over previous
#include <cuda_runtime.h>
#include <cuda_fp16.h>
#include <math.h>
#include <stdint.h>

// Problem dims (fixed by the reference)
#define Bb 4
#define Tt 2048
#define Hh 1024
#define Nn 16
#define CHUNKS 128
#define Lchunk (Tt / CHUNKS)   // 16
#define Mrows (Bb * Tt)        // 8192
#define Kd Hh                  // 1024 (plain fp16 GEMM K)

// ---------------- scratch (module-scope device memory) ----------------
__device__ __half g_Ah[(size_t)Mrows * Kd];              // x in fp16   16MB
__device__ __half g_Bh[(size_t)Hh * Kd];                 // W in fp16    2MB
__device__ float2 g_zu[(size_t)Mrows * Hh];              // packed {dt,u} 64MB
__device__ float g_q[(size_t)Bb * CHUNKS * Nn * Hh];     // 32MB
__device__ float g_S[(size_t)Bb * CHUNKS * Hh];          //  2MB
__device__ float g_sinit[(size_t)Bb * CHUNKS * Nn * Hh]; // 32MB

__device__ __forceinline__ float ex2f(float x) {
    float y;
    asm("ex2.approx.ftz.f32 %0, %1;" : "=f"(y) : "f"(x));
    return y;
}
__device__ __forceinline__ float softplusf(float z) {
    float az = fabsf(z);
    return fmaxf(z, 0.0f) + log1pf(__expf(-az));
}
__device__ __forceinline__ void cp_async16(uint32_t saddr, const void* gptr) {
    asm volatile("cp.async.cg.shared.global [%0], [%1], 16;"
                 :: "r"(saddr), "l"(__cvta_generic_to_global(gptr)) : "memory");
}
__device__ __forceinline__ void ldmatrix_x4(uint32_t* r, uint32_t saddr) {
    asm volatile("ldmatrix.sync.aligned.m8n8.x4.shared.b16 {%0,%1,%2,%3}, [%4];"
                 : "=r"(r[0]), "=r"(r[1]), "=r"(r[2]), "=r"(r[3]) : "r"(saddr));
}
__device__ __forceinline__ void mma16816(float* c, const uint32_t* a, uint32_t b0, uint32_t b1) {
    asm volatile(
        "mma.sync.aligned.m16n8k16.row.col.f32.f16.f16.f32 "
        "{%0,%1,%2,%3}, {%4,%5,%6,%7}, {%8,%9}, {%0,%1,%2,%3};"
        : "+f"(c[0]), "+f"(c[1]), "+f"(c[2]), "+f"(c[3])
        : "r"(a[0]), "r"(a[1]), "r"(a[2]), "r"(a[3]), "r"(b0), "r"(b1));
}

// ---------------------------------------------------------------------------
// fp32 -> fp16 conversion kernels
// ---------------------------------------------------------------------------
__global__ __launch_bounds__(256)
void convert_x_kernel(const float* __restrict__ x) {
    size_t i = (size_t)blockIdx.x * 256 + threadIdx.x;  // one float4
    float4 v = ((const float4*)x)[i];
    uint2 hi;
    hi.x = ((uint32_t)__half_as_ushort(__float2half_rn(v.y)) << 16) |
           __half_as_ushort(__float2half_rn(v.x));
    hi.y = ((uint32_t)__half_as_ushort(__float2half_rn(v.w)) << 16) |
           __half_as_ushort(__float2half_rn(v.z));
    *(uint2*)(g_Ah + i * 4) = hi;
}

__global__ __launch_bounds__(256)
void convert_w_kernel(const float* __restrict__ W) {
    size_t i = (size_t)blockIdx.x * 256 + threadIdx.x;
    float4 v = ((const float4*)W)[i];
    uint2 hi;
    hi.x = ((uint32_t)__half_as_ushort(__float2half_rn(v.y)) << 16) |
           __half_as_ushort(__float2half_rn(v.x));
    hi.y = ((uint32_t)__half_as_ushort(__float2half_rn(v.w)) << 16) |
           __half_as_ushort(__float2half_rn(v.z));
    *(uint2*)(g_Bh + i * 4) = hi;
}

// ---------------------------------------------------------------------------
// mma.sync fp16 GEMM: z = x @ W^T ; zu = {softplus(z+b), u}
// CTA tile 128x128, BK=32, 8 warps (2m x 4n), warp tile 64x32.
// 4-stage cp.async pipeline, single __syncthreads per K-iter.
// ---------------------------------------------------------------------------
#define GBM 128
#define GBN 128
#define GBK 32
#define NKT (Kd / GBK)             // 32
#define NSTAGE 4
#define A_ELEMS (GBM * GBK)        // 4096 halves = 8KB
#define STAGE_ELEMS (2 * A_ELEMS)  // 8192 halves = 16KB
#define STAGE_BYTES (STAGE_ELEMS * 2)
#define GEMM_DYN_SMEM (NSTAGE * STAGE_BYTES)  // 64KB

// smem byte offset within a 128x32 fp16 tile: row r (0..127), 16B-chunk c (0..3)
__device__ __forceinline__ uint32_t swz(int r, int c) {
    return (uint32_t)(r * 64 + ((c ^ ((r >> 1) & 3)) << 4));
}

__global__ __launch_bounds__(256, 2)
void gemm_mma_kernel(const float* __restrict__ x, const float* __restrict__ bdt) {
    extern __shared__ __align__(16) char dsm[];

    const int tid = threadIdx.x;
    const int wid = tid >> 5, lane = tid & 31;
    const int n0 = blockIdx.x * GBN;
    const int m0 = blockIdx.y * GBM;
    const int wm = (wid >> 2) * 64;   // warp m offset
    const int wn = (wid & 3) * 32;    // warp n offset

    const uint32_t s0 = (uint32_t)__cvta_generic_to_shared(dsm);

    const __half* Abase = g_Ah + (size_t)m0 * Kd;
    const __half* Bbase = g_Bh + (size_t)n0 * Kd;

    const int ch0 = tid;
    auto issue_loads = [&](int kt, int stage) {
        const uint32_t sA = s0 + stage * STAGE_BYTES;
        const uint32_t sB = sA + A_ELEMS * 2;
        const __half* Ag = Abase + kt * GBK;
        const __half* Bg = Bbase + kt * GBK;
#pragma unroll
        for (int i = 0; i < 2; i++) {
            int ch = ch0 + i * 256;
            int r = ch >> 2, c = ch & 3;
            cp_async16(sA + swz(r, c), Ag + (size_t)r * Kd + c * 8);
        }
#pragma unroll
        for (int i = 0; i < 2; i++) {
            int ch = ch0 + i * 256;
            int r = ch >> 2, c = ch & 3;
            cp_async16(sB + swz(r, c), Bg + (size_t)r * Kd + c * 8);
        }
        asm volatile("cp.async.commit_group;" ::: "memory");
    };

    float acc[4][4][4];
#pragma unroll
    for (int i = 0; i < 4; i++)
#pragma unroll
        for (int j = 0; j < 4; j++)
#pragma unroll
            for (int k = 0; k < 4; k++) acc[i][j][k] = 0.0f;

#pragma unroll
    for (int s = 0; s < NSTAGE - 1; s++) issue_loads(s, s);

    const int lrow = lane & 15;
    const int lkh  = (lane >> 4) & 1;

    for (int kt = 0; kt < NKT; kt++) {
        asm volatile("cp.async.wait_group %0;" :: "n"(NSTAGE - 2) : "memory");
        __syncthreads();

        if (kt + NSTAGE - 1 < NKT) {
            issue_loads(kt + NSTAGE - 1, (kt + NSTAGE - 1) & (NSTAGE - 1));
        } else {
            asm volatile("cp.async.commit_group;" ::: "memory");
        }

        const int stage = kt & (NSTAGE - 1);
        const uint32_t sA = s0 + stage * STAGE_BYTES;
        const uint32_t sB = sA + A_ELEMS * 2;

#pragma unroll
        for (int ks = 0; ks < 2; ks++) {
            const int c16 = ks * 2 + lkh;
            uint32_t a[4][4];
#pragma unroll
            for (int mb = 0; mb < 4; mb++)
                ldmatrix_x4(a[mb], sA + swz(wm + mb * 16 + lrow, c16));
            uint32_t bf[2][4];
#pragma unroll
            for (int nb = 0; nb < 2; nb++)
                ldmatrix_x4(bf[nb], sB + swz(wn + nb * 16 + lrow, c16));
#pragma unroll
            for (int mb = 0; mb < 4; mb++)
#pragma unroll
                for (int j = 0; j < 4; j++)
                    mma16816(acc[mb][j], a[mb], bf[j >> 1][j & 1], bf[j >> 1][(j & 1) + 2]);
        }
    }

    // Epilogue: bias + softplus; pack {dt, u} -> g_zu
    const int g = lane >> 2;
    const int t = lane & 3;
#pragma unroll
    for (int j = 0; j < 4; j++) {
        const int h = n0 + wn + j * 8 + 2 * t;
        const float b0 = __ldg(&bdt[h]);
        const float b1 = __ldg(&bdt[h + 1]);
#pragma unroll
        for (int mb = 0; mb < 4; mb++) {
            const int m = m0 + wm + mb * 16 + g;
            const float2 u0 = *(const float2*)(x + (size_t)m * Hh + h);
            const float2 u1 = *(const float2*)(x + (size_t)(m + 8) * Hh + h);
            float4 o0, o1;
            o0.x = softplusf(acc[mb][j][0] + b0); o0.y = u0.x;
            o0.z = softplusf(acc[mb][j][1] + b1); o0.w = u0.y;
            o1.x = softplusf(acc[mb][j][2] + b0); o1.y = u1.x;
            o1.z = softplusf(acc[mb][j][3] + b1); o1.w = u1.y;
            *(float4*)(&g_zu[(size_t)m * Hh + h])       = o0;
            *(float4*)(&g_zu[(size_t)(m + 8) * Hh + h]) = o1;
        }
    }
}

// ---------------------------------------------------------------------------
// Phase 1: per (b, h, chunk) recurrence from zero state -> q, S
// ---------------------------------------------------------------------------
__global__ __launch_bounds__(256)
void phase1_kernel(const float* __restrict__ Alog, const float* __restrict__ Bmat) {
    const int h = blockIdx.x * 256 + threadIdx.x;
    const int c = blockIdx.y;
    const int b = blockIdx.z;

    float A2[Nn], Bv[Nn], s[Nn];
#pragma unroll
    for (int n = 0; n < Nn; ++n) {
        A2[n] = -expf(Alog[h * Nn + n]) * 1.4426950408889634f;
        Bv[n] = Bmat[h * Nn + n];
        s[n] = 0.0f;
    }
    const float2* zp = g_zu + ((size_t)b * Tt + c * Lchunk) * Hh + h;

    float S = 0.0f;
    float2 cur = zp[0];
#pragma unroll 4
    for (int tt = 0; tt < Lchunk; ++tt) {
        float2 nxt = (tt + 1 < Lchunk) ? zp[(size_t)(tt + 1) * Hh] : cur;
        const float dtv = cur.x;
        const float du  = dtv * cur.y;
        S += dtv;
#pragma unroll
        for (int n = 0; n < Nn; ++n) {
            const float e = ex2f(dtv * A2[n]);
            s[n] = fmaf(e, s[n], Bv[n] * du);
        }
        cur = nxt;
    }
#pragma unroll
    for (int n = 0; n < Nn; ++n)
        g_q[(((size_t)(b * CHUNKS + c)) * Nn + n) * Hh + h] = s[n];
    g_S[(size_t)(b * CHUNKS + c) * Hh + h] = S;
}

// ---------------------------------------------------------------------------
// Phase 2: sequential combine across chunks per (b, h, n)
// ---------------------------------------------------------------------------
__global__ __launch_bounds__(256)
void phase2_kernel(const float* __restrict__ Alog, float* __restrict__ out,
                   int write_state) {
    const int idx = blockIdx.x * 256 + threadIdx.x;
    const int h = idx & (Hh - 1);
    const int u = idx >> 10;
    const int n = u & (Nn - 1);
    const int b = u >> 4;

    const float A2 = -expf(Alog[h * Nn + n]) * 1.4426950408889634f;
    float s = 0.0f;
    for (int c = 0; c < CHUNKS; ++c) {
        const size_t qi = (((size_t)(b * CHUNKS + c)) * Nn + n) * Hh + h;
        g_sinit[qi] = s;
        const float Sc = g_S[(size_t)(b * CHUNKS + c) * Hh + h];
        const float e = ex2f(Sc * A2);
        s = fmaf(e, s, g_q[qi]);
    }
    if (write_state) {
        out[(size_t)Mrows * Hh + ((size_t)b * Hh + h) * Nn + n] = s;
    }
}

// ---------------------------------------------------------------------------
// Phase 3: re-run each chunk from its true initial state, emit y
// ---------------------------------------------------------------------------
__global__ __launch_bounds__(256)
void phase3_kernel(const float* __restrict__ Alog, const float* __restrict__ Bmat,
                   const float* __restrict__ Cmat, const float* __restrict__ Dvec,
                   float* __restrict__ out) {
    const int h = blockIdx.x * 256 + threadIdx.x;
    const int c = blockIdx.y;
    const int b = blockIdx.z;

    float A2[Nn], Bv[Nn], Cv[Nn], s[Nn];
#pragma unroll
    for (int n = 0; n < Nn; ++n) {
        A2[n] = -expf(Alog[h * Nn + n]) * 1.4426950408889634f;
        Bv[n] = Bmat[h * Nn + n];
        Cv[n] = Cmat[h * Nn + n];
        s[n]  = g_sinit[(((size_t)(b * CHUNKS + c)) * Nn + n) * Hh + h];
    }
    const float Dh = Dvec[h];
    const size_t base = ((size_t)b * Tt + c * Lchunk) * Hh + h;
    const float2* zp = g_zu + base;
    float* yp = out + base;

    float2 cur = zp[0];
#pragma unroll 4
    for (int tt = 0; tt < Lchunk; ++tt) {
        float2 nxt = (tt + 1 < Lchunk) ? zp[(size_t)(tt + 1) * Hh] : cur;
        const float dtv = cur.x;
        const float uv  = cur.y;
        const float du  = dtv * uv;
        float y = Dh * uv;
#pragma unroll
        for (int n = 0; n < Nn; ++n) {
            const float e = ex2f(dtv * A2[n]);
            s[n] = fmaf(e, s[n], Bv[n] * du);
            y = fmaf(s[n], Cv[n], y);
        }
        yp[(size_t)tt * Hh] = y;
        cur = nxt;
    }
}

// ---------------------------------------------------------------------------
extern "C" void kernel_launch(void* const* d_in, const int* in_sizes, int n_in,
                              void* d_out, int out_size) {
    const float* x     = (const float*)d_in[0];
    const float* A_log = (const float*)d_in[1];
    const float* B_mat = (const float*)d_in[2];
    const float* C_mat = (const float*)d_in[3];
    const float* D_vec = (const float*)d_in[4];
    const float* W_dt  = (const float*)d_in[5];
    const float* b_dt  = (const float*)d_in[6];
    float* out = (float*)d_out;

    // fp16 operand prep
    convert_x_kernel<<<(Mrows * Hh / 4) / 256, 256>>>(x);
    convert_w_kernel<<<(Hh * Hh / 4) / 256, 256>>>(W_dt);

    // tensor-core GEMM + softplus epilogue -> packed g_zu {dt,u}
    static int smem_set = 0;
    if (!smem_set) {
        cudaFuncSetAttribute(gemm_mma_kernel,
                             cudaFuncAttributeMaxDynamicSharedMemorySize, GEMM_DYN_SMEM);
        smem_set = 1;
    }
    gemm_mma_kernel<<<dim3(Hh / GBN, Mrows / GBM), 256, GEMM_DYN_SMEM>>>(x, b_dt);

    // chunked scan
    phase1_kernel<<<dim3(Hh / 256, CHUNKS, Bb), 256>>>(A_log, B_mat);

    const int write_state =
        ((size_t)out_size >= (size_t)Mrows * Hh + (size_t)Bb * Hh * Nn) ? 1 : 0;
    phase2_kernel<<<(Bb * Hh * Nn) / 256, 256>>>(A_log, out, write_state);

    phase3_kernel<<<dim3(Hh / 256, CHUNKS, Bb), 256>>>(A_log, B_mat, C_mat, D_vec, out);
}

// round 6
// speedup vs baseline: 3.0903x; 1.6265x over previous
#include <cuda_runtime.h>
#include <cuda_fp16.h>
#include <math.h>
#include <stdint.h>

// Problem dims (fixed by the reference)
#define Bb 4
#define Tt 2048
#define Hh 1024
#define Nn 16
#define CHUNKS 64
#define Lchunk (Tt / CHUNKS)   // 32
#define Mrows (Bb * Tt)        // 8192
#define Kd Hh                  // 1024 (plain fp16 GEMM K)

// ---------------- scratch (module-scope device memory) ----------------
__device__ __half g_Ah[(size_t)Mrows * Kd];              // x in fp16   16MB
__device__ __half g_Bh[(size_t)Hh * Kd];                 // W in fp16    2MB
__device__ float2 g_zu[(size_t)Mrows * Hh];              // packed {dt,u} 64MB
__device__ float g_q[(size_t)Bb * CHUNKS * Nn * Hh];     // 16MB
__device__ float g_S[(size_t)Bb * CHUNKS * Hh];          //  1MB
__device__ float g_sinit[(size_t)Bb * CHUNKS * Nn * Hh]; // 16MB

__device__ __forceinline__ float ex2f(float x) {
    float y;
    asm("ex2.approx.ftz.f32 %0, %1;" : "=f"(y) : "f"(x));
    return y;
}
__device__ __forceinline__ float softplusf(float z) {
    float az = fabsf(z);
    return fmaxf(z, 0.0f) + log1pf(__expf(-az));
}
__device__ __forceinline__ void cp_async16(uint32_t saddr, const void* gptr) {
    asm volatile("cp.async.cg.shared.global [%0], [%1], 16;"
                 :: "r"(saddr), "l"(__cvta_generic_to_global(gptr)) : "memory");
}
__device__ __forceinline__ void ldmatrix_x4(uint32_t* r, uint32_t saddr) {
    asm volatile("ldmatrix.sync.aligned.m8n8.x4.shared.b16 {%0,%1,%2,%3}, [%4];"
                 : "=r"(r[0]), "=r"(r[1]), "=r"(r[2]), "=r"(r[3]) : "r"(saddr));
}
__device__ __forceinline__ void mma16816(float* c, const uint32_t* a, uint32_t b0, uint32_t b1) {
    asm volatile(
        "mma.sync.aligned.m16n8k16.row.col.f32.f16.f16.f32 "
        "{%0,%1,%2,%3}, {%4,%5,%6,%7}, {%8,%9}, {%0,%1,%2,%3};"
        : "+f"(c[0]), "+f"(c[1]), "+f"(c[2]), "+f"(c[3])
        : "r"(a[0]), "r"(a[1]), "r"(a[2]), "r"(a[3]), "r"(b0), "r"(b1));
}

// ---------------------------------------------------------------------------
// fp32 -> fp16 conversion kernels
// ---------------------------------------------------------------------------
__global__ __launch_bounds__(256)
void convert_x_kernel(const float* __restrict__ x) {
    size_t i = (size_t)blockIdx.x * 256 + threadIdx.x;  // one float4
    float4 v = ((const float4*)x)[i];
    uint2 hi;
    hi.x = ((uint32_t)__half_as_ushort(__float2half_rn(v.y)) << 16) |
           __half_as_ushort(__float2half_rn(v.x));
    hi.y = ((uint32_t)__half_as_ushort(__float2half_rn(v.w)) << 16) |
           __half_as_ushort(__float2half_rn(v.z));
    *(uint2*)(g_Ah + i * 4) = hi;
}

__global__ __launch_bounds__(256)
void convert_w_kernel(const float* __restrict__ W) {
    size_t i = (size_t)blockIdx.x * 256 + threadIdx.x;
    float4 v = ((const float4*)W)[i];
    uint2 hi;
    hi.x = ((uint32_t)__half_as_ushort(__float2half_rn(v.y)) << 16) |
           __half_as_ushort(__float2half_rn(v.x));
    hi.y = ((uint32_t)__half_as_ushort(__float2half_rn(v.w)) << 16) |
           __half_as_ushort(__float2half_rn(v.z));
    *(uint2*)(g_Bh + i * 4) = hi;
}

// ---------------------------------------------------------------------------
// mma.sync fp16 GEMM: z = x @ W^T ; zu = {softplus(z+b), u}
// ---------------------------------------------------------------------------
#define GBM 128
#define GBN 128
#define GBK 32
#define NKT (Kd / GBK)             // 32
#define NSTAGE 4
#define A_ELEMS (GBM * GBK)        // 4096 halves = 8KB
#define STAGE_ELEMS (2 * A_ELEMS)  // 16KB
#define STAGE_BYTES (STAGE_ELEMS * 2)
#define GEMM_DYN_SMEM (NSTAGE * STAGE_BYTES)  // 64KB

__device__ __forceinline__ uint32_t swz(int r, int c) {
    return (uint32_t)(r * 64 + ((c ^ ((r >> 1) & 3)) << 4));
}

__global__ __launch_bounds__(256, 2)
void gemm_mma_kernel(const float* __restrict__ x, const float* __restrict__ bdt) {
    extern __shared__ __align__(16) char dsm[];

    const int tid = threadIdx.x;
    const int wid = tid >> 5, lane = tid & 31;
    const int n0 = blockIdx.x * GBN;
    const int m0 = blockIdx.y * GBM;
    const int wm = (wid >> 2) * 64;
    const int wn = (wid & 3) * 32;

    const uint32_t s0 = (uint32_t)__cvta_generic_to_shared(dsm);

    const __half* Abase = g_Ah + (size_t)m0 * Kd;
    const __half* Bbase = g_Bh + (size_t)n0 * Kd;

    const int ch0 = tid;
    auto issue_loads = [&](int kt, int stage) {
        const uint32_t sA = s0 + stage * STAGE_BYTES;
        const uint32_t sB = sA + A_ELEMS * 2;
        const __half* Ag = Abase + kt * GBK;
        const __half* Bg = Bbase + kt * GBK;
#pragma unroll
        for (int i = 0; i < 2; i++) {
            int ch = ch0 + i * 256;
            int r = ch >> 2, c = ch & 3;
            cp_async16(sA + swz(r, c), Ag + (size_t)r * Kd + c * 8);
        }
#pragma unroll
        for (int i = 0; i < 2; i++) {
            int ch = ch0 + i * 256;
            int r = ch >> 2, c = ch & 3;
            cp_async16(sB + swz(r, c), Bg + (size_t)r * Kd + c * 8);
        }
        asm volatile("cp.async.commit_group;" ::: "memory");
    };

    float acc[4][4][4];
#pragma unroll
    for (int i = 0; i < 4; i++)
#pragma unroll
        for (int j = 0; j < 4; j++)
#pragma unroll
            for (int k = 0; k < 4; k++) acc[i][j][k] = 0.0f;

#pragma unroll
    for (int s = 0; s < NSTAGE - 1; s++) issue_loads(s, s);

    const int lrow = lane & 15;
    const int lkh  = (lane >> 4) & 1;

    for (int kt = 0; kt < NKT; kt++) {
        asm volatile("cp.async.wait_group %0;" :: "n"(NSTAGE - 2) : "memory");
        __syncthreads();

        if (kt + NSTAGE - 1 < NKT) {
            issue_loads(kt + NSTAGE - 1, (kt + NSTAGE - 1) & (NSTAGE - 1));
        } else {
            asm volatile("cp.async.commit_group;" ::: "memory");
        }

        const int stage = kt & (NSTAGE - 1);
        const uint32_t sA = s0 + stage * STAGE_BYTES;
        const uint32_t sB = sA + A_ELEMS * 2;

#pragma unroll
        for (int ks = 0; ks < 2; ks++) {
            const int c16 = ks * 2 + lkh;
            uint32_t a[4][4];
#pragma unroll
            for (int mb = 0; mb < 4; mb++)
                ldmatrix_x4(a[mb], sA + swz(wm + mb * 16 + lrow, c16));
            uint32_t bf[2][4];
#pragma unroll
            for (int nb = 0; nb < 2; nb++)
                ldmatrix_x4(bf[nb], sB + swz(wn + nb * 16 + lrow, c16));
#pragma unroll
            for (int mb = 0; mb < 4; mb++)
#pragma unroll
                for (int j = 0; j < 4; j++)
                    mma16816(acc[mb][j], a[mb], bf[j >> 1][j & 1], bf[j >> 1][(j & 1) + 2]);
        }
    }

    // Epilogue: bias + softplus; pack {dt, u} -> g_zu
    const int g = lane >> 2;
    const int t = lane & 3;
#pragma unroll
    for (int j = 0; j < 4; j++) {
        const int h = n0 + wn + j * 8 + 2 * t;
        const float b0 = __ldg(&bdt[h]);
        const float b1 = __ldg(&bdt[h + 1]);
#pragma unroll
        for (int mb = 0; mb < 4; mb++) {
            const int m = m0 + wm + mb * 16 + g;
            const float2 u0 = *(const float2*)(x + (size_t)m * Hh + h);
            const float2 u1 = *(const float2*)(x + (size_t)(m + 8) * Hh + h);
            float4 o0, o1;
            o0.x = softplusf(acc[mb][j][0] + b0); o0.y = u0.x;
            o0.z = softplusf(acc[mb][j][1] + b1); o0.w = u0.y;
            o1.x = softplusf(acc[mb][j][2] + b0); o1.y = u1.x;
            o1.z = softplusf(acc[mb][j][3] + b1); o1.w = u1.y;
            *(float4*)(&g_zu[(size_t)m * Hh + h])       = o0;
            *(float4*)(&g_zu[(size_t)(m + 8) * Hh + h]) = o1;
        }
    }
}

// ---------------------------------------------------------------------------
// Scan phases with cp.async slab staging.
// Slab: [Lchunk][256] float2 = 64KB. Whole chunk staged up front -> full MLP.
// ---------------------------------------------------------------------------
#define SLAB_BYTES (Lchunk * 256 * 8)          // 64KB
#define SLAB_CHUNKS16 (SLAB_BYTES / 16)        // 4096
#define CH_PER_THR (SLAB_CHUNKS16 / 256)       // 16

__device__ __forceinline__ void stage_slab(uint32_t sbase, const float2* __restrict__ src,
                                           int tid) {
#pragma unroll
    for (int i = 0; i < CH_PER_THR; i++) {
        int ch = tid + i * 256;                // 0..4095
        int t = ch >> 7;                       // row
        int off = (ch & 127) << 4;             // byte offset in row (2048B rows)
        cp_async16(sbase + t * 2048 + off,
                   (const char*)(src + (size_t)t * Hh) + off);
    }
    asm volatile("cp.async.commit_group;" ::: "memory");
    asm volatile("cp.async.wait_group 0;" ::: "memory");
}

__global__ __launch_bounds__(256)
void phase1_kernel(const float* __restrict__ Alog, const float* __restrict__ Bmat) {
    extern __shared__ __align__(16) float2 slab[];  // [Lchunk][256]
    const int tid = threadIdx.x;
    const int h0 = blockIdx.x * 256;
    const int h = h0 + tid;
    const int c = blockIdx.y;
    const int b = blockIdx.z;

    const uint32_t sbase = (uint32_t)__cvta_generic_to_shared(slab);
    stage_slab(sbase, g_zu + ((size_t)b * Tt + c * Lchunk) * Hh + h0, tid);

    float A2[Nn], Bv[Nn], s[Nn];
#pragma unroll
    for (int i = 0; i < 4; i++) {
        float4 av = *(const float4*)(Alog + h * Nn + i * 4);
        float4 bv = *(const float4*)(Bmat + h * Nn + i * 4);
        A2[i*4+0] = -expf(av.x) * 1.4426950408889634f;
        A2[i*4+1] = -expf(av.y) * 1.4426950408889634f;
        A2[i*4+2] = -expf(av.z) * 1.4426950408889634f;
        A2[i*4+3] = -expf(av.w) * 1.4426950408889634f;
        Bv[i*4+0] = bv.x; Bv[i*4+1] = bv.y; Bv[i*4+2] = bv.z; Bv[i*4+3] = bv.w;
    }
#pragma unroll
    for (int n = 0; n < Nn; ++n) s[n] = 0.0f;

    __syncthreads();

    float S = 0.0f;
#pragma unroll 8
    for (int tt = 0; tt < Lchunk; ++tt) {
        const float2 cur = slab[tt * 256 + tid];
        const float dtv = cur.x;
        const float du  = dtv * cur.y;
        S += dtv;
#pragma unroll
        for (int n = 0; n < Nn; ++n) {
            const float e = ex2f(dtv * A2[n]);
            s[n] = fmaf(e, s[n], Bv[n] * du);
        }
    }
#pragma unroll
    for (int n = 0; n < Nn; ++n)
        g_q[(((size_t)(b * CHUNKS + c)) * Nn + n) * Hh + h] = s[n];
    g_S[(size_t)(b * CHUNKS + c) * Hh + h] = S;
}

__global__ __launch_bounds__(256)
void phase2_kernel(const float* __restrict__ Alog, float* __restrict__ out,
                   int write_state) {
    const int idx = blockIdx.x * 256 + threadIdx.x;
    const int h = idx & (Hh - 1);
    const int u = idx >> 10;
    const int n = u & (Nn - 1);
    const int b = u >> 4;

    const float A2 = -expf(Alog[h * Nn + n]) * 1.4426950408889634f;
    float s = 0.0f;
    for (int c = 0; c < CHUNKS; ++c) {
        const size_t qi = (((size_t)(b * CHUNKS + c)) * Nn + n) * Hh + h;
        g_sinit[qi] = s;
        const float Sc = g_S[(size_t)(b * CHUNKS + c) * Hh + h];
        const float e = ex2f(Sc * A2);
        s = fmaf(e, s, g_q[qi]);
    }
    if (write_state) {
        out[(size_t)Mrows * Hh + ((size_t)b * Hh + h) * Nn + n] = s;
    }
}

__global__ __launch_bounds__(256)
void phase3_kernel(const float* __restrict__ Alog, const float* __restrict__ Bmat,
                   const float* __restrict__ Cmat, const float* __restrict__ Dvec,
                   float* __restrict__ out) {
    extern __shared__ __align__(16) float2 slab[];  // [Lchunk][256]
    const int tid = threadIdx.x;
    const int h0 = blockIdx.x * 256;
    const int h = h0 + tid;
    const int c = blockIdx.y;
    const int b = blockIdx.z;

    const uint32_t sbase = (uint32_t)__cvta_generic_to_shared(slab);
    const size_t base = ((size_t)b * Tt + c * Lchunk) * Hh + h0;
    stage_slab(sbase, g_zu + base, tid);

    float A2[Nn], Bv[Nn], Cv[Nn], s[Nn];
#pragma unroll
    for (int i = 0; i < 4; i++) {
        float4 av = *(const float4*)(Alog + h * Nn + i * 4);
        float4 bv = *(const float4*)(Bmat + h * Nn + i * 4);
        float4 cv = *(const float4*)(Cmat + h * Nn + i * 4);
        A2[i*4+0] = -expf(av.x) * 1.4426950408889634f;
        A2[i*4+1] = -expf(av.y) * 1.4426950408889634f;
        A2[i*4+2] = -expf(av.z) * 1.4426950408889634f;
        A2[i*4+3] = -expf(av.w) * 1.4426950408889634f;
        Bv[i*4+0] = bv.x; Bv[i*4+1] = bv.y; Bv[i*4+2] = bv.z; Bv[i*4+3] = bv.w;
        Cv[i*4+0] = cv.x; Cv[i*4+1] = cv.y; Cv[i*4+2] = cv.z; Cv[i*4+3] = cv.w;
    }
#pragma unroll
    for (int n = 0; n < Nn; ++n)
        s[n] = g_sinit[(((size_t)(b * CHUNKS + c)) * Nn + n) * Hh + h];

    const float Dh = Dvec[h];
    float* yp = out + base + tid;

    __syncthreads();

#pragma unroll 8
    for (int tt = 0; tt < Lchunk; ++tt) {
        const float2 cur = slab[tt * 256 + tid];
        const float dtv = cur.x;
        const float uv  = cur.y;
        const float du  = dtv * uv;
        float y = Dh * uv;
#pragma unroll
        for (int n = 0; n < Nn; ++n) {
            const float e = ex2f(dtv * A2[n]);
            s[n] = fmaf(e, s[n], Bv[n] * du);
            y = fmaf(s[n], Cv[n], y);
        }
        yp[(size_t)tt * Hh] = y;
    }
}

// ---------------------------------------------------------------------------
extern "C" void kernel_launch(void* const* d_in, const int* in_sizes, int n_in,
                              void* d_out, int out_size) {
    const float* x     = (const float*)d_in[0];
    const float* A_log = (const float*)d_in[1];
    const float* B_mat = (const float*)d_in[2];
    const float* C_mat = (const float*)d_in[3];
    const float* D_vec = (const float*)d_in[4];
    const float* W_dt  = (const float*)d_in[5];
    const float* b_dt  = (const float*)d_in[6];
    float* out = (float*)d_out;

    static int attr_set = 0;
    if (!attr_set) {
        cudaFuncSetAttribute(gemm_mma_kernel,
                             cudaFuncAttributeMaxDynamicSharedMemorySize, GEMM_DYN_SMEM);
        cudaFuncSetAttribute(phase1_kernel,
                             cudaFuncAttributeMaxDynamicSharedMemorySize, SLAB_BYTES);
        cudaFuncSetAttribute(phase3_kernel,
                             cudaFuncAttributeMaxDynamicSharedMemorySize, SLAB_BYTES);
        attr_set = 1;
    }

    // fp16 operand prep
    convert_x_kernel<<<(Mrows * Hh / 4) / 256, 256>>>(x);
    convert_w_kernel<<<(Hh * Hh / 4) / 256, 256>>>(W_dt);

    // tensor-core GEMM + softplus epilogue -> packed g_zu {dt,u}
    gemm_mma_kernel<<<dim3(Hh / GBN, Mrows / GBM), 256, GEMM_DYN_SMEM>>>(x, b_dt);

    // chunked scan
    phase1_kernel<<<dim3(Hh / 256, CHUNKS, Bb), 256, SLAB_BYTES>>>(A_log, B_mat);

    const int write_state =
        ((size_t)out_size >= (size_t)Mrows * Hh + (size_t)Bb * Hh * Nn) ? 1 : 0;
    phase2_kernel<<<(Bb * Hh * Nn) / 256, 256>>>(A_log, out, write_state);

    phase3_kernel<<<dim3(Hh / 256, CHUNKS, Bb), 256, SLAB_BYTES>>>(A_log, B_mat, C_mat, D_vec, out);
}

// round 8
// speedup vs baseline: 3.1649x; 1.0241x over previous
#include <cuda_runtime.h>
#include <cuda_fp16.h>
#include <math.h>
#include <stdint.h>

// Problem dims (fixed by the reference)
#define Bb 4
#define Tt 2048
#define Hh 1024
#define Nn 16
#define CHUNKS 64
#define Lchunk (Tt / CHUNKS)   // 32
#define Mrows (Bb * Tt)        // 8192
#define Kd Hh                  // 1024 (plain fp16 GEMM K)

// ---------------- scratch (module-scope device memory) ----------------
__device__ __half g_Ah[(size_t)Mrows * Kd];              // x in fp16   16MB
__device__ __half g_Bh[(size_t)Hh * Kd];                 // W in fp16    2MB
__device__ float2 g_zu[(size_t)Mrows * Hh];              // packed {dt,u} 64MB
__device__ float g_q[(size_t)Bb * CHUNKS * Nn * Hh];     // q~ 16MB
__device__ float g_S[(size_t)Bb * CHUNKS * Hh];          //  1MB
__device__ float g_sinit[(size_t)Bb * CHUNKS * Nn * Hh]; // sinit~ 16MB

__device__ __forceinline__ float ex2f(float x) {
    float y;
    asm("ex2.approx.ftz.f32 %0, %1;" : "=f"(y) : "f"(x));
    return y;
}
// two exp2's through one MUFU op (f16x2). f16 output precision — y path only.
__device__ __forceinline__ float2 ex2_f16x2(float a0, float a1) {
    uint32_t hp;
    asm("cvt.rn.f16x2.f32 %0, %1, %2;" : "=r"(hp) : "f"(a1), "f"(a0));  // lo=a0, hi=a1
    asm("ex2.approx.f16x2 %0, %0;" : "+r"(hp));
    float e0, e1;
    asm("{\n\t.reg .b16 lo, hi;\n\tmov.b32 {lo, hi}, %2;\n\t"
        "cvt.f32.f16 %0, lo;\n\tcvt.f32.f16 %1, hi;\n\t}"
        : "=f"(e0), "=f"(e1) : "r"(hp));
    return make_float2(e0, e1);
}
__device__ __forceinline__ float softplusf(float z) {
    float az = fabsf(z);
    return fmaxf(z, 0.0f) + log1pf(__expf(-az));
}
__device__ __forceinline__ void cp_async16(uint32_t saddr, const void* gptr) {
    asm volatile("cp.async.cg.shared.global [%0], [%1], 16;"
                 :: "r"(saddr), "l"(__cvta_generic_to_global(gptr)) : "memory");
}
__device__ __forceinline__ void ldmatrix_x4(uint32_t* r, uint32_t saddr) {
    asm volatile("ldmatrix.sync.aligned.m8n8.x4.shared.b16 {%0,%1,%2,%3}, [%4];"
                 : "=r"(r[0]), "=r"(r[1]), "=r"(r[2]), "=r"(r[3]) : "r"(saddr));
}
__device__ __forceinline__ void mma16816(float* c, const uint32_t* a, uint32_t b0, uint32_t b1) {
    asm volatile(
        "mma.sync.aligned.m16n8k16.row.col.f32.f16.f16.f32 "
        "{%0,%1,%2,%3}, {%4,%5,%6,%7}, {%8,%9}, {%0,%1,%2,%3};"
        : "+f"(c[0]), "+f"(c[1]), "+f"(c[2]), "+f"(c[3])
        : "r"(a[0]), "r"(a[1]), "r"(a[2]), "r"(a[3]), "r"(b0), "r"(b1));
}

// ---------------------------------------------------------------------------
// fp32 -> fp16 conversion kernels
// ---------------------------------------------------------------------------
__global__ __launch_bounds__(256)
void convert_x_kernel(const float* __restrict__ x) {
    size_t i = (size_t)blockIdx.x * 256 + threadIdx.x;  // one float4
    float4 v = ((const float4*)x)[i];
    uint2 hi;
    hi.x = ((uint32_t)__half_as_ushort(__float2half_rn(v.y)) << 16) |
           __half_as_ushort(__float2half_rn(v.x));
    hi.y = ((uint32_t)__half_as_ushort(__float2half_rn(v.w)) << 16) |
           __half_as_ushort(__float2half_rn(v.z));
    *(uint2*)(g_Ah + i * 4) = hi;
}

__global__ __launch_bounds__(256)
void convert_w_kernel(const float* __restrict__ W) {
    size_t i = (size_t)blockIdx.x * 256 + threadIdx.x;
    float4 v = ((const float4*)W)[i];
    uint2 hi;
    hi.x = ((uint32_t)__half_as_ushort(__float2half_rn(v.y)) << 16) |
           __half_as_ushort(__float2half_rn(v.x));
    hi.y = ((uint32_t)__half_as_ushort(__float2half_rn(v.w)) << 16) |
           __half_as_ushort(__float2half_rn(v.z));
    *(uint2*)(g_Bh + i * 4) = hi;
}

// ---------------------------------------------------------------------------
// mma.sync fp16 GEMM: z = x @ W^T ; zu = {softplus(z+b), u}
// ---------------------------------------------------------------------------
#define GBM 128
#define GBN 128
#define GBK 32
#define NKT (Kd / GBK)             // 32
#define NSTAGE 4
#define A_ELEMS (GBM * GBK)        // 8KB
#define STAGE_ELEMS (2 * A_ELEMS)
#define STAGE_BYTES (STAGE_ELEMS * 2)
#define GEMM_DYN_SMEM (NSTAGE * STAGE_BYTES)  // 64KB

__device__ __forceinline__ uint32_t swz(int r, int c) {
    return (uint32_t)(r * 64 + ((c ^ ((r >> 1) & 3)) << 4));
}

__global__ __launch_bounds__(256, 2)
void gemm_mma_kernel(const float* __restrict__ x, const float* __restrict__ bdt) {
    extern __shared__ __align__(16) char dsm[];

    const int tid = threadIdx.x;
    const int wid = tid >> 5, lane = tid & 31;
    const int n0 = blockIdx.x * GBN;
    const int m0 = blockIdx.y * GBM;
    const int wm = (wid >> 2) * 64;
    const int wn = (wid & 3) * 32;

    const uint32_t s0 = (uint32_t)__cvta_generic_to_shared(dsm);

    const __half* Abase = g_Ah + (size_t)m0 * Kd;
    const __half* Bbase = g_Bh + (size_t)n0 * Kd;

    const int ch0 = tid;
    auto issue_loads = [&](int kt, int stage) {
        const uint32_t sA = s0 + stage * STAGE_BYTES;
        const uint32_t sB = sA + A_ELEMS * 2;
        const __half* Ag = Abase + kt * GBK;
        const __half* Bg = Bbase + kt * GBK;
#pragma unroll
        for (int i = 0; i < 2; i++) {
            int ch = ch0 + i * 256;
            int r = ch >> 2, c = ch & 3;
            cp_async16(sA + swz(r, c), Ag + (size_t)r * Kd + c * 8);
        }
#pragma unroll
        for (int i = 0; i < 2; i++) {
            int ch = ch0 + i * 256;
            int r = ch >> 2, c = ch & 3;
            cp_async16(sB + swz(r, c), Bg + (size_t)r * Kd + c * 8);
        }
        asm volatile("cp.async.commit_group;" ::: "memory");
    };

    float acc[4][4][4];
#pragma unroll
    for (int i = 0; i < 4; i++)
#pragma unroll
        for (int j = 0; j < 4; j++)
#pragma unroll
            for (int k = 0; k < 4; k++) acc[i][j][k] = 0.0f;

#pragma unroll
    for (int s = 0; s < NSTAGE - 1; s++) issue_loads(s, s);

    const int lrow = lane & 15;
    const int lkh  = (lane >> 4) & 1;

    for (int kt = 0; kt < NKT; kt++) {
        asm volatile("cp.async.wait_group %0;" :: "n"(NSTAGE - 2) : "memory");
        __syncthreads();

        if (kt + NSTAGE - 1 < NKT) {
            issue_loads(kt + NSTAGE - 1, (kt + NSTAGE - 1) & (NSTAGE - 1));
        } else {
            asm volatile("cp.async.commit_group;" ::: "memory");
        }

        const int stage = kt & (NSTAGE - 1);
        const uint32_t sA = s0 + stage * STAGE_BYTES;
        const uint32_t sB = sA + A_ELEMS * 2;

#pragma unroll
        for (int ks = 0; ks < 2; ks++) {
            const int c16 = ks * 2 + lkh;
            uint32_t a[4][4];
#pragma unroll
            for (int mb = 0; mb < 4; mb++)
                ldmatrix_x4(a[mb], sA + swz(wm + mb * 16 + lrow, c16));
            uint32_t bf[2][4];
#pragma unroll
            for (int nb = 0; nb < 2; nb++)
                ldmatrix_x4(bf[nb], sB + swz(wn + nb * 16 + lrow, c16));
#pragma unroll
            for (int mb = 0; mb < 4; mb++)
#pragma unroll
                for (int j = 0; j < 4; j++)
                    mma16816(acc[mb][j], a[mb], bf[j >> 1][j & 1], bf[j >> 1][(j & 1) + 2]);
        }
    }

    const int g = lane >> 2;
    const int t = lane & 3;
#pragma unroll
    for (int j = 0; j < 4; j++) {
        const int h = n0 + wn + j * 8 + 2 * t;
        const float b0 = __ldg(&bdt[h]);
        const float b1 = __ldg(&bdt[h + 1]);
#pragma unroll
        for (int mb = 0; mb < 4; mb++) {
            const int m = m0 + wm + mb * 16 + g;
            const float2 u0 = *(const float2*)(x + (size_t)m * Hh + h);
            const float2 u1 = *(const float2*)(x + (size_t)(m + 8) * Hh + h);
            float4 o0, o1;
            o0.x = softplusf(acc[mb][j][0] + b0); o0.y = u0.x;
            o0.z = softplusf(acc[mb][j][1] + b1); o0.w = u0.y;
            o1.x = softplusf(acc[mb][j][2] + b0); o1.y = u1.x;
            o1.z = softplusf(acc[mb][j][3] + b1); o1.w = u1.y;
            *(float4*)(&g_zu[(size_t)m * Hh + h])       = o0;
            *(float4*)(&g_zu[(size_t)(m + 8) * Hh + h]) = o1;
        }
    }
}

// ---------------------------------------------------------------------------
// Scan phases. State transform: s~ = s / Bv, so s~ = e*s~ + du (du scalar).
// phase1 (state path): fp32 ex2.  phase3 (y path): f16x2 ex2.
// ---------------------------------------------------------------------------
#define SLAB_BYTES (Lchunk * 256 * 8)          // 64KB
#define SLAB_CHUNKS16 (SLAB_BYTES / 16)        // 4096
#define CH_PER_THR (SLAB_CHUNKS16 / 256)       // 16

__device__ __forceinline__ void stage_slab(uint32_t sbase, const float2* __restrict__ src,
                                           int tid) {
#pragma unroll
    for (int i = 0; i < CH_PER_THR; i++) {
        int ch = tid + i * 256;                // 0..4095
        int t = ch >> 7;                       // row
        int off = (ch & 127) << 4;             // byte offset in row (2048B rows)
        cp_async16(sbase + t * 2048 + off,
                   (const char*)(src + (size_t)t * Hh) + off);
    }
    asm volatile("cp.async.commit_group;" ::: "memory");
    asm volatile("cp.async.wait_group 0;" ::: "memory");
}

__global__ __launch_bounds__(256)
void phase1_kernel(const float* __restrict__ Alog) {
    extern __shared__ __align__(16) float2 slab[];  // [Lchunk][256]
    const int tid = threadIdx.x;
    const int h0 = blockIdx.x * 256;
    const int h = h0 + tid;
    const int c = blockIdx.y;
    const int b = blockIdx.z;

    const uint32_t sbase = (uint32_t)__cvta_generic_to_shared(slab);
    stage_slab(sbase, g_zu + ((size_t)b * Tt + c * Lchunk) * Hh + h0, tid);

    float A2[Nn], s[Nn];
#pragma unroll
    for (int i = 0; i < 4; i++) {
        float4 av = *(const float4*)(Alog + h * Nn + i * 4);
        A2[i*4+0] = -expf(av.x) * 1.4426950408889634f;
        A2[i*4+1] = -expf(av.y) * 1.4426950408889634f;
        A2[i*4+2] = -expf(av.z) * 1.4426950408889634f;
        A2[i*4+3] = -expf(av.w) * 1.4426950408889634f;
    }
#pragma unroll
    for (int n = 0; n < Nn; ++n) s[n] = 0.0f;

    __syncthreads();

    float S = 0.0f;
#pragma unroll 8
    for (int tt = 0; tt < Lchunk; ++tt) {
        const float2 cur = slab[tt * 256 + tid];
        const float dtv = cur.x;
        const float du  = dtv * cur.y;
        S += dtv;
#pragma unroll
        for (int n = 0; n < Nn; ++n) {
            const float e = ex2f(dtv * A2[n]);   // fp32 precision: feeds state output
            s[n] = fmaf(e, s[n], du);
        }
    }
#pragma unroll
    for (int n = 0; n < Nn; ++n)
        g_q[(((size_t)(b * CHUNKS + c)) * Nn + n) * Hh + h] = s[n];
    g_S[(size_t)(b * CHUNKS + c) * Hh + h] = S;
}

__global__ __launch_bounds__(256)
void phase2_kernel(const float* __restrict__ Alog, const float* __restrict__ Bmat,
                   float* __restrict__ out, int write_state) {
    const int idx = blockIdx.x * 256 + threadIdx.x;
    const int h = idx & (Hh - 1);
    const int u = idx >> 10;
    const int n = u & (Nn - 1);
    const int b = u >> 4;

    const float A2 = -expf(Alog[h * Nn + n]) * 1.4426950408889634f;
    float s = 0.0f;
    for (int c = 0; c < CHUNKS; ++c) {
        const size_t qi = (((size_t)(b * CHUNKS + c)) * Nn + n) * Hh + h;
        g_sinit[qi] = s;
        const float Sc = g_S[(size_t)(b * CHUNKS + c) * Hh + h];
        const float e = ex2f(Sc * A2);
        s = fmaf(e, s, g_q[qi]);
    }
    if (write_state) {
        // back to true state: s = s~ * Bv
        out[(size_t)Mrows * Hh + ((size_t)b * Hh + h) * Nn + n] = s * Bmat[h * Nn + n];
    }
}

__global__ __launch_bounds__(256)
void phase3_kernel(const float* __restrict__ Alog, const float* __restrict__ Bmat,
                   const float* __restrict__ Cmat, const float* __restrict__ Dvec,
                   float* __restrict__ out) {
    extern __shared__ __align__(16) float2 slab[];  // [Lchunk][256]
    const int tid = threadIdx.x;
    const int h0 = blockIdx.x * 256;
    const int h = h0 + tid;
    const int c = blockIdx.y;
    const int b = blockIdx.z;

    const uint32_t sbase = (uint32_t)__cvta_generic_to_shared(slab);
    const size_t base = ((size_t)b * Tt + c * Lchunk) * Hh + h0;
    stage_slab(sbase, g_zu + base, tid);

    float A2[Nn], CB[Nn], s[Nn];
#pragma unroll
    for (int i = 0; i < 4; i++) {
        float4 av = *(const float4*)(Alog + h * Nn + i * 4);
        float4 bv = *(const float4*)(Bmat + h * Nn + i * 4);
        float4 cv = *(const float4*)(Cmat + h * Nn + i * 4);
        A2[i*4+0] = -expf(av.x) * 1.4426950408889634f;
        A2[i*4+1] = -expf(av.y) * 1.4426950408889634f;
        A2[i*4+2] = -expf(av.z) * 1.4426950408889634f;
        A2[i*4+3] = -expf(av.w) * 1.4426950408889634f;
        CB[i*4+0] = bv.x * cv.x; CB[i*4+1] = bv.y * cv.y;
        CB[i*4+2] = bv.z * cv.z; CB[i*4+3] = bv.w * cv.w;
    }
#pragma unroll
    for (int n = 0; n < Nn; ++n)
        s[n] = g_sinit[(((size_t)(b * CHUNKS + c)) * Nn + n) * Hh + h];

    const float Dh = Dvec[h];
    float* yp = out + base + tid;

    __syncthreads();

#pragma unroll 8
    for (int tt = 0; tt < Lchunk; ++tt) {
        const float2 cur = slab[tt * 256 + tid];
        const float dtv = cur.x;
        const float uv  = cur.y;
        const float du  = dtv * uv;
        float y = Dh * uv;
#pragma unroll
        for (int p = 0; p < Nn / 2; ++p) {
            const float2 e = ex2_f16x2(dtv * A2[2*p], dtv * A2[2*p+1]);  // y path: f16 ok
            s[2*p]   = fmaf(e.x, s[2*p],   du);
            s[2*p+1] = fmaf(e.y, s[2*p+1], du);
            y = fmaf(s[2*p],   CB[2*p],   y);
            y = fmaf(s[2*p+1], CB[2*p+1], y);
        }
        yp[(size_t)tt * Hh] = y;
    }
}

// ---------------------------------------------------------------------------
extern "C" void kernel_launch(void* const* d_in, const int* in_sizes, int n_in,
                              void* d_out, int out_size) {
    const float* x     = (const float*)d_in[0];
    const float* A_log = (const float*)d_in[1];
    const float* B_mat = (const float*)d_in[2];
    const float* C_mat = (const float*)d_in[3];
    const float* D_vec = (const float*)d_in[4];
    const float* W_dt  = (const float*)d_in[5];
    const float* b_dt  = (const float*)d_in[6];
    float* out = (float*)d_out;

    static int attr_set = 0;
    if (!attr_set) {
        cudaFuncSetAttribute(gemm_mma_kernel,
                             cudaFuncAttributeMaxDynamicSharedMemorySize, GEMM_DYN_SMEM);
        cudaFuncSetAttribute(phase1_kernel,
                             cudaFuncAttributeMaxDynamicSharedMemorySize, SLAB_BYTES);
        cudaFuncSetAttribute(phase3_kernel,
                             cudaFuncAttributeMaxDynamicSharedMemorySize, SLAB_BYTES);
        attr_set = 1;
    }

    // fp16 operand prep
    convert_x_kernel<<<(Mrows * Hh / 4) / 256, 256>>>(x);
    convert_w_kernel<<<(Hh * Hh / 4) / 256, 256>>>(W_dt);

    // tensor-core GEMM + softplus epilogue -> packed g_zu {dt,u}
    gemm_mma_kernel<<<dim3(Hh / GBN, Mrows / GBM), 256, GEMM_DYN_SMEM>>>(x, b_dt);

    // chunked scan (s~ space)
    phase1_kernel<<<dim3(Hh / 256, CHUNKS, Bb), 256, SLAB_BYTES>>>(A_log);

    const int write_state =
        ((size_t)out_size >= (size_t)Mrows * Hh + (size_t)Bb * Hh * Nn) ? 1 : 0;
    phase2_kernel<<<(Bb * Hh * Nn) / 256, 256>>>(A_log, B_mat, out, write_state);

    phase3_kernel<<<dim3(Hh / 256, CHUNKS, Bb), 256, SLAB_BYTES>>>(A_log, B_mat, C_mat, D_vec, out);
}

// round 9
// speedup vs baseline: 3.5065x; 1.1080x over previous
#include <cuda_runtime.h>
#include <cuda_fp16.h>
#include <math.h>
#include <stdint.h>

// Problem dims (fixed by the reference)
#define Bb 4
#define Tt 2048
#define Hh 1024
#define Nn 16
#define CHUNKS 64
#define Lchunk (Tt / CHUNKS)   // 32
#define Mrows (Bb * Tt)        // 8192
#define Kd Hh                  // 1024 (plain fp16 GEMM K)

// ---------------- scratch (module-scope device memory) ----------------
__device__ __half g_Ah[(size_t)Mrows * Kd];              // x in fp16   16MB
__device__ __half g_Bh[(size_t)Hh * Kd];                 // W in fp16    2MB
__device__ float g_dt[(size_t)Mrows * Hh];               // dt fp32     32MB
__device__ float g_q[(size_t)Bb * CHUNKS * Nn * Hh];     // q~ 16MB
__device__ float g_S[(size_t)Bb * CHUNKS * Hh];          //  1MB
__device__ float g_sinit[(size_t)Bb * CHUNKS * Nn * Hh]; // sinit~ 16MB

__device__ __forceinline__ float ex2f(float x) {
    float y;
    asm("ex2.approx.ftz.f32 %0, %1;" : "=f"(y) : "f"(x));
    return y;
}
// two exp2's through one MUFU op (f16x2). f16 output precision — y path only.
__device__ __forceinline__ float2 ex2_f16x2(float a0, float a1) {
    uint32_t hp;
    asm("cvt.rn.f16x2.f32 %0, %1, %2;" : "=r"(hp) : "f"(a1), "f"(a0));  // lo=a0, hi=a1
    asm("ex2.approx.f16x2 %0, %0;" : "+r"(hp));
    float e0, e1;
    asm("{\n\t.reg .b16 lo, hi;\n\tmov.b32 {lo, hi}, %2;\n\t"
        "cvt.f32.f16 %0, lo;\n\tcvt.f32.f16 %1, hi;\n\t}"
        : "=f"(e0), "=f"(e1) : "r"(hp));
    return make_float2(e0, e1);
}
__device__ __forceinline__ float softplusf(float z) {
    float az = fabsf(z);
    return fmaxf(z, 0.0f) + log1pf(__expf(-az));
}
__device__ __forceinline__ void cp_async16(uint32_t saddr, const void* gptr) {
    asm volatile("cp.async.cg.shared.global [%0], [%1], 16;"
                 :: "r"(saddr), "l"(__cvta_generic_to_global(gptr)) : "memory");
}
__device__ __forceinline__ void ldmatrix_x4(uint32_t* r, uint32_t saddr) {
    asm volatile("ldmatrix.sync.aligned.m8n8.x4.shared.b16 {%0,%1,%2,%3}, [%4];"
                 : "=r"(r[0]), "=r"(r[1]), "=r"(r[2]), "=r"(r[3]) : "r"(saddr));
}
__device__ __forceinline__ void mma16816(float* c, const uint32_t* a, uint32_t b0, uint32_t b1) {
    asm volatile(
        "mma.sync.aligned.m16n8k16.row.col.f32.f16.f16.f32 "
        "{%0,%1,%2,%3}, {%4,%5,%6,%7}, {%8,%9}, {%0,%1,%2,%3};"
        : "+f"(c[0]), "+f"(c[1]), "+f"(c[2]), "+f"(c[3])
        : "r"(a[0]), "r"(a[1]), "r"(a[2]), "r"(a[3]), "r"(b0), "r"(b1));
}

// ---------------------------------------------------------------------------
// fp32 -> fp16 conversion kernels
// ---------------------------------------------------------------------------
__global__ __launch_bounds__(256)
void convert_x_kernel(const float* __restrict__ x) {
    size_t i = (size_t)blockIdx.x * 256 + threadIdx.x;  // one float4
    float4 v = ((const float4*)x)[i];
    uint2 hi;
    hi.x = ((uint32_t)__half_as_ushort(__float2half_rn(v.y)) << 16) |
           __half_as_ushort(__float2half_rn(v.x));
    hi.y = ((uint32_t)__half_as_ushort(__float2half_rn(v.w)) << 16) |
           __half_as_ushort(__float2half_rn(v.z));
    *(uint2*)(g_Ah + i * 4) = hi;
}

__global__ __launch_bounds__(256)
void convert_w_kernel(const float* __restrict__ W) {
    size_t i = (size_t)blockIdx.x * 256 + threadIdx.x;
    float4 v = ((const float4*)W)[i];
    uint2 hi;
    hi.x = ((uint32_t)__half_as_ushort(__float2half_rn(v.y)) << 16) |
           __half_as_ushort(__float2half_rn(v.x));
    hi.y = ((uint32_t)__half_as_ushort(__float2half_rn(v.w)) << 16) |
           __half_as_ushort(__float2half_rn(v.z));
    *(uint2*)(g_Bh + i * 4) = hi;
}

// ---------------------------------------------------------------------------
// mma.sync fp16 GEMM: dt = softplus(x @ W^T + b)   (fp32 out, no u packing)
// CTA tile 128x128, BK=64, 8 warps (2m x 4n), 3-stage cp.async (96KB smem).
// ---------------------------------------------------------------------------
#define GBM 128
#define GBN 128
#define GBK 64
#define NKT (Kd / GBK)             // 16
#define NSTAGE 3
#define A_BYTES (GBM * GBK * 2)    // 16KB
#define STAGE_BYTES (2 * A_BYTES)  // 32KB (A + B)
#define GEMM_DYN_SMEM (NSTAGE * STAGE_BYTES)  // 96KB

// swizzled byte offset in a 128x64-half tile: row r (0..127), 16B-chunk c (0..7)
__device__ __forceinline__ uint32_t swz64(int r, int c) {
    return (uint32_t)(r * 128 + ((c ^ (r & 7)) << 4));
}

__global__ __launch_bounds__(256, 2)
void gemm_mma_kernel(const float* __restrict__ bdt) {
    extern __shared__ __align__(16) char dsm[];

    const int tid = threadIdx.x;
    const int wid = tid >> 5, lane = tid & 31;
    const int n0 = blockIdx.x * GBN;
    const int m0 = blockIdx.y * GBM;
    const int wm = (wid >> 2) * 64;
    const int wn = (wid & 3) * 32;

    const uint32_t s0 = (uint32_t)__cvta_generic_to_shared(dsm);

    const __half* Abase = g_Ah + (size_t)m0 * Kd;
    const __half* Bbase = g_Bh + (size_t)n0 * Kd;

    // per stage: A 1024 chunks + B 1024 chunks; 256 threads -> 4 A + 4 B each
    auto issue_loads = [&](int kt, int stage) {
        const uint32_t sA = s0 + stage * STAGE_BYTES;
        const uint32_t sB = sA + A_BYTES;
        const __half* Ag = Abase + kt * GBK;
        const __half* Bg = Bbase + kt * GBK;
#pragma unroll
        for (int i = 0; i < 4; i++) {
            int ch = tid + i * 256;            // 0..1023
            int r = ch >> 3, c = ch & 7;
            cp_async16(sA + swz64(r, c), Ag + (size_t)r * Kd + c * 8);
        }
#pragma unroll
        for (int i = 0; i < 4; i++) {
            int ch = tid + i * 256;
            int r = ch >> 3, c = ch & 7;
            cp_async16(sB + swz64(r, c), Bg + (size_t)r * Kd + c * 8);
        }
        asm volatile("cp.async.commit_group;" ::: "memory");
    };

    float acc[4][4][4];
#pragma unroll
    for (int i = 0; i < 4; i++)
#pragma unroll
        for (int j = 0; j < 4; j++)
#pragma unroll
            for (int k = 0; k < 4; k++) acc[i][j][k] = 0.0f;

    issue_loads(0, 0);
    issue_loads(1, 1);

    const int lrow = lane & 15;
    const int lkh  = (lane >> 4) & 1;

    int stage = 0;
    for (int kt = 0; kt < NKT; kt++) {
        asm volatile("cp.async.wait_group %0;" :: "n"(NSTAGE - 2) : "memory");
        __syncthreads();

        if (kt + NSTAGE - 1 < NKT) {
            int ns = stage + 2; if (ns >= NSTAGE) ns -= NSTAGE;
            issue_loads(kt + NSTAGE - 1, ns);
        } else {
            asm volatile("cp.async.commit_group;" ::: "memory");
        }

        const uint32_t sA = s0 + stage * STAGE_BYTES;
        const uint32_t sB = sA + A_BYTES;

#pragma unroll
        for (int ks = 0; ks < 4; ks++) {       // 4 x K=16
            const int c16 = ks * 2 + lkh;
            uint32_t a[4][4];
#pragma unroll
            for (int mb = 0; mb < 4; mb++)
                ldmatrix_x4(a[mb], sA + swz64(wm + mb * 16 + lrow, c16));
            uint32_t bf[2][4];
#pragma unroll
            for (int nb = 0; nb < 2; nb++)
                ldmatrix_x4(bf[nb], sB + swz64(wn + nb * 16 + lrow, c16));
#pragma unroll
            for (int mb = 0; mb < 4; mb++)
#pragma unroll
                for (int j = 0; j < 4; j++)
                    mma16816(acc[mb][j], a[mb], bf[j >> 1][j & 1], bf[j >> 1][(j & 1) + 2]);
        }
        if (++stage >= NSTAGE) stage = 0;
    }

    // Epilogue: bias + softplus; float2 stores to g_dt [m][h]
    const int g = lane >> 2;
    const int t = lane & 3;
#pragma unroll
    for (int j = 0; j < 4; j++) {
        const int h = n0 + wn + j * 8 + 2 * t;
        const float b0 = __ldg(&bdt[h]);
        const float b1 = __ldg(&bdt[h + 1]);
#pragma unroll
        for (int mb = 0; mb < 4; mb++) {
            const int m = m0 + wm + mb * 16 + g;
            float2 v0, v1;
            v0.x = softplusf(acc[mb][j][0] + b0);
            v0.y = softplusf(acc[mb][j][1] + b1);
            v1.x = softplusf(acc[mb][j][2] + b0);
            v1.y = softplusf(acc[mb][j][3] + b1);
            *(float2*)(&g_dt[(size_t)m * Hh + h])       = v0;
            *(float2*)(&g_dt[(size_t)(m + 8) * Hh + h]) = v1;
        }
    }
}

// ---------------------------------------------------------------------------
// Scan phases. State transform: s~ = s / Bv, so s~ = e*s~ + du (du scalar).
// Dual slab staging: dt slab + x slab (both fp32, 32KB each).
// phase1 (state path): fp32 ex2.  phase3 (y path): f16x2 ex2.
// ---------------------------------------------------------------------------
#define SLAB_FLOATS (Lchunk * 256)             // 8192 floats = 32KB per slab
#define SLAB_BYTES_TOT (2 * SLAB_FLOATS * 4)   // 64KB
#define CH_PER_SLAB (SLAB_FLOATS / 4 / 256)    // 8 x 16B chunks per thread

__device__ __forceinline__ void stage_two_slabs(uint32_t sD, uint32_t sU,
                                                const float* __restrict__ dsrc,
                                                const float* __restrict__ usrc,
                                                int tid) {
#pragma unroll
    for (int i = 0; i < CH_PER_SLAB; i++) {
        int ch = tid + i * 256;                // 0..2047
        int t = ch >> 6;                       // row (64 chunks of 16B per 1KB row)
        int off = (ch & 63) << 4;
        cp_async16(sD + t * 1024 + off, (const char*)(dsrc + (size_t)t * Hh) + off);
    }
#pragma unroll
    for (int i = 0; i < CH_PER_SLAB; i++) {
        int ch = tid + i * 256;
        int t = ch >> 6;
        int off = (ch & 63) << 4;
        cp_async16(sU + t * 1024 + off, (const char*)(usrc + (size_t)t * Hh) + off);
    }
    asm volatile("cp.async.commit_group;" ::: "memory");
    asm volatile("cp.async.wait_group 0;" ::: "memory");
}

__global__ __launch_bounds__(256)
void phase1_kernel(const float* __restrict__ x, const float* __restrict__ Alog) {
    extern __shared__ __align__(16) float slabs[];  // [2][Lchunk][256]
    float* slabD = slabs;
    float* slabU = slabs + SLAB_FLOATS;
    const int tid = threadIdx.x;
    const int h0 = blockIdx.x * 256;
    const int h = h0 + tid;
    const int c = blockIdx.y;
    const int b = blockIdx.z;

    const uint32_t sD = (uint32_t)__cvta_generic_to_shared(slabD);
    const uint32_t sU = (uint32_t)__cvta_generic_to_shared(slabU);
    const size_t base = ((size_t)b * Tt + c * Lchunk) * Hh + h0;
    stage_two_slabs(sD, sU, g_dt + base, x + base, tid);

    float A2[Nn], s[Nn];
#pragma unroll
    for (int i = 0; i < 4; i++) {
        float4 av = *(const float4*)(Alog + h * Nn + i * 4);
        A2[i*4+0] = -expf(av.x) * 1.4426950408889634f;
        A2[i*4+1] = -expf(av.y) * 1.4426950408889634f;
        A2[i*4+2] = -expf(av.z) * 1.4426950408889634f;
        A2[i*4+3] = -expf(av.w) * 1.4426950408889634f;
    }
#pragma unroll
    for (int n = 0; n < Nn; ++n) s[n] = 0.0f;

    __syncthreads();

    float S = 0.0f;
#pragma unroll 8
    for (int tt = 0; tt < Lchunk; ++tt) {
        const float dtv = slabD[tt * 256 + tid];
        const float uv  = slabU[tt * 256 + tid];
        const float du  = dtv * uv;
        S += dtv;
#pragma unroll
        for (int n = 0; n < Nn; ++n) {
            const float e = ex2f(dtv * A2[n]);   // fp32: feeds state output
            s[n] = fmaf(e, s[n], du);
        }
    }
#pragma unroll
    for (int n = 0; n < Nn; ++n)
        g_q[(((size_t)(b * CHUNKS + c)) * Nn + n) * Hh + h] = s[n];
    g_S[(size_t)(b * CHUNKS + c) * Hh + h] = S;
}

__global__ __launch_bounds__(256)
void phase2_kernel(const float* __restrict__ Alog, const float* __restrict__ Bmat,
                   float* __restrict__ out, int write_state) {
    const int idx = blockIdx.x * 256 + threadIdx.x;
    const int h = idx & (Hh - 1);
    const int u = idx >> 10;
    const int n = u & (Nn - 1);
    const int b = u >> 4;

    const float A2 = -expf(Alog[h * Nn + n]) * 1.4426950408889634f;
    float s = 0.0f;
    for (int c = 0; c < CHUNKS; ++c) {
        const size_t qi = (((size_t)(b * CHUNKS + c)) * Nn + n) * Hh + h;
        g_sinit[qi] = s;
        const float Sc = g_S[(size_t)(b * CHUNKS + c) * Hh + h];
        const float e = ex2f(Sc * A2);
        s = fmaf(e, s, g_q[qi]);
    }
    if (write_state) {
        out[(size_t)Mrows * Hh + ((size_t)b * Hh + h) * Nn + n] = s * Bmat[h * Nn + n];
    }
}

__global__ __launch_bounds__(256)
void phase3_kernel(const float* __restrict__ x, const float* __restrict__ Alog,
                   const float* __restrict__ Bmat, const float* __restrict__ Cmat,
                   const float* __restrict__ Dvec, float* __restrict__ out) {
    extern __shared__ __align__(16) float slabs[];  // [2][Lchunk][256]
    float* slabD = slabs;
    float* slabU = slabs + SLAB_FLOATS;
    const int tid = threadIdx.x;
    const int h0 = blockIdx.x * 256;
    const int h = h0 + tid;
    const int c = blockIdx.y;
    const int b = blockIdx.z;

    const uint32_t sD = (uint32_t)__cvta_generic_to_shared(slabD);
    const uint32_t sU = (uint32_t)__cvta_generic_to_shared(slabU);
    const size_t base = ((size_t)b * Tt + c * Lchunk) * Hh + h0;
    stage_two_slabs(sD, sU, g_dt + base, x + base, tid);

    float A2[Nn], CB[Nn], s[Nn];
#pragma unroll
    for (int i = 0; i < 4; i++) {
        float4 av = *(const float4*)(Alog + h * Nn + i * 4);
        float4 bv = *(const float4*)(Bmat + h * Nn + i * 4);
        float4 cv = *(const float4*)(Cmat + h * Nn + i * 4);
        A2[i*4+0] = -expf(av.x) * 1.4426950408889634f;
        A2[i*4+1] = -expf(av.y) * 1.4426950408889634f;
        A2[i*4+2] = -expf(av.z) * 1.4426950408889634f;
        A2[i*4+3] = -expf(av.w) * 1.4426950408889634f;
        CB[i*4+0] = bv.x * cv.x; CB[i*4+1] = bv.y * cv.y;
        CB[i*4+2] = bv.z * cv.z; CB[i*4+3] = bv.w * cv.w;
    }
#pragma unroll
    for (int n = 0; n < Nn; ++n)
        s[n] = g_sinit[(((size_t)(b * CHUNKS + c)) * Nn + n) * Hh + h];

    const float Dh = Dvec[h];
    float* yp = out + base + tid;

    __syncthreads();

#pragma unroll 8
    for (int tt = 0; tt < Lchunk; ++tt) {
        const float dtv = slabD[tt * 256 + tid];
        const float uv  = slabU[tt * 256 + tid];
        const float du  = dtv * uv;
        float y = Dh * uv;
#pragma unroll
        for (int p = 0; p < Nn / 2; ++p) {
            const float2 e = ex2_f16x2(dtv * A2[2*p], dtv * A2[2*p+1]);  // y path: f16 ok
            s[2*p]   = fmaf(e.x, s[2*p],   du);
            s[2*p+1] = fmaf(e.y, s[2*p+1], du);
            y = fmaf(s[2*p],   CB[2*p],   y);
            y = fmaf(s[2*p+1], CB[2*p+1], y);
        }
        yp[(size_t)tt * Hh] = y;
    }
}

// ---------------------------------------------------------------------------
extern "C" void kernel_launch(void* const* d_in, const int* in_sizes, int n_in,
                              void* d_out, int out_size) {
    const float* x     = (const float*)d_in[0];
    const float* A_log = (const float*)d_in[1];
    const float* B_mat = (const float*)d_in[2];
    const float* C_mat = (const float*)d_in[3];
    const float* D_vec = (const float*)d_in[4];
    const float* W_dt  = (const float*)d_in[5];
    const float* b_dt  = (const float*)d_in[6];
    float* out = (float*)d_out;

    static int attr_set = 0;
    if (!attr_set) {
        cudaFuncSetAttribute(gemm_mma_kernel,
                             cudaFuncAttributeMaxDynamicSharedMemorySize, GEMM_DYN_SMEM);
        cudaFuncSetAttribute(phase1_kernel,
                             cudaFuncAttributeMaxDynamicSharedMemorySize, SLAB_BYTES_TOT);
        cudaFuncSetAttribute(phase3_kernel,
                             cudaFuncAttributeMaxDynamicSharedMemorySize, SLAB_BYTES_TOT);
        attr_set = 1;
    }

    // fp16 operand prep
    convert_x_kernel<<<(Mrows * Hh / 4) / 256, 256>>>(x);
    convert_w_kernel<<<(Hh * Hh / 4) / 256, 256>>>(W_dt);

    // tensor-core GEMM + softplus epilogue -> g_dt (fp32)
    gemm_mma_kernel<<<dim3(Hh / GBN, Mrows / GBM), 256, GEMM_DYN_SMEM>>>(b_dt);

    // chunked scan (s~ space)
    phase1_kernel<<<dim3(Hh / 256, CHUNKS, Bb), 256, SLAB_BYTES_TOT>>>(x, A_log);

    const int write_state =
        ((size_t)out_size >= (size_t)Mrows * Hh + (size_t)Bb * Hh * Nn) ? 1 : 0;
    phase2_kernel<<<(Bb * Hh * Nn) / 256, 256>>>(A_log, B_mat, out, write_state);

    phase3_kernel<<<dim3(Hh / 256, CHUNKS, Bb), 256, SLAB_BYTES_TOT>>>(x, A_log, B_mat, C_mat, D_vec, out);
}